// round 1
// baseline (speedup 1.0000x reference)
#include <cuda_runtime.h>
#include <math.h>

// Problem constants (fixed shapes)
#define B_  16
#define C_  128
#define H_  64
#define W_  64
#define G_  4
#define CG_ 32
#define HW_ 4096      // H_*W_
#define HS_ 128
#define WS_ 128

// Scratch (static device globals; no runtime allocation)
__device__ float d_Wt[C_ * C_];           // Wt[k][c] = w_proj[c,k] * bn_scale[c]
__device__ float d_tb[C_];                // folded bias
__device__ float d_p[B_ * G_ * HW_ * CG_];// p in (b,g,pix,cg) layout, 33.5MB
__device__ float d_off[B_ * 8 * HW_];     // tanh offsets, NCHW (B,2G,H,W)

// ---------------------------------------------------------------------------
// K0: fold BN into transposed 1x1 weights + bias
// ---------------------------------------------------------------------------
__global__ void k0_prep(const float* __restrict__ w_proj,
                        const float* __restrict__ gamma,
                        const float* __restrict__ beta,
                        const float* __restrict__ mean,
                        const float* __restrict__ var) {
    int idx = blockIdx.x * blockDim.x + threadIdx.x;   // 16384 threads
    if (idx >= C_ * C_) return;
    int k = idx >> 7;
    int c = idx & 127;
    float s = gamma[c] / sqrtf(var[c] + 1e-5f);
    d_Wt[k * C_ + c] = w_proj[c * C_ + k] * s;
    if (idx < C_) {
        d_tb[idx] = beta[idx] - mean[idx] * (gamma[idx] / sqrtf(var[idx] + 1e-5f));
    }
}

// ---------------------------------------------------------------------------
// K1: 1x1 conv (GEMM M=pixels, N=128, K=128) + bias + SiLU
//     output layout: d_p[((b*G+g)*HW + pix)*32 + cg]
//     block: 128 pixels x 128 channels, 256 threads, 8x8 frags
// ---------------------------------------------------------------------------
__global__ __launch_bounds__(256, 2) void k1_gemm(const float* __restrict__ x) {
    int b = blockIdx.y;
    int pix0 = blockIdx.x * 128;
    __shared__ float As[16][128];   // k x pix
    __shared__ float Bs[16][132];   // k x c (padded)

    const float* xb = x + (size_t)b * C_ * HW_;
    int tid = threadIdx.x;
    int tx = tid & 15;              // pixel-frag group
    int ty = tid >> 4;              // channel-frag group
    int px0 = tx * 4;
    int cy0 = ty * 4;

    float acc[8][8];
#pragma unroll
    for (int i = 0; i < 8; i++)
#pragma unroll
        for (int j = 0; j < 8; j++) acc[i][j] = 0.f;

    for (int k0 = 0; k0 < C_; k0 += 16) {
        // load A tile: 16 x 128 = 512 float4
#pragma unroll
        for (int i = 0; i < 2; i++) {
            int idx = tid + i * 256;
            int kk = idx >> 5, pq = idx & 31;
            *(float4*)&As[kk][pq * 4] =
                *(const float4*)&xb[(size_t)(k0 + kk) * HW_ + pix0 + pq * 4];
        }
        // load B tile from pre-transposed Wt (coalesced)
#pragma unroll
        for (int i = 0; i < 2; i++) {
            int idx = tid + i * 256;
            int kk = idx >> 5, cq = idx & 31;
            *(float4*)&Bs[kk][cq * 4] =
                *(const float4*)&d_Wt[(k0 + kk) * C_ + cq * 4];
        }
        __syncthreads();
#pragma unroll
        for (int kk = 0; kk < 16; kk++) {
            float a[8], bb[8];
            *(float4*)&a[0] = *(float4*)&As[kk][px0];
            *(float4*)&a[4] = *(float4*)&As[kk][px0 + 64];
            *(float4*)&bb[0] = *(float4*)&Bs[kk][cy0];
            *(float4*)&bb[4] = *(float4*)&Bs[kk][cy0 + 64];
#pragma unroll
            for (int i = 0; i < 8; i++)
#pragma unroll
                for (int j = 0; j < 8; j++) acc[i][j] += a[i] * bb[j];
        }
        __syncthreads();
    }

    // epilogue: bias + SiLU, store to group-NHWC
    float tbv[8];
#pragma unroll
    for (int q = 0; q < 4; q++) { tbv[q] = d_tb[cy0 + q]; tbv[4 + q] = d_tb[cy0 + 64 + q]; }

#pragma unroll
    for (int i = 0; i < 8; i++) {
        int pix = pix0 + px0 + ((i < 4) ? i : 64 + (i - 4));
#pragma unroll
        for (int jh = 0; jh < 2; jh++) {
            int c = cy0 + jh * 64;
            float4 v;
            float u;
            u = acc[i][jh * 4 + 0] + tbv[jh * 4 + 0]; v.x = u * (1.f / (1.f + __expf(-u)));
            u = acc[i][jh * 4 + 1] + tbv[jh * 4 + 1]; v.y = u * (1.f / (1.f + __expf(-u)));
            u = acc[i][jh * 4 + 2] + tbv[jh * 4 + 2]; v.z = u * (1.f / (1.f + __expf(-u)));
            u = acc[i][jh * 4 + 3] + tbv[jh * 4 + 3]; v.w = u * (1.f / (1.f + __expf(-u)));
            int g = c >> 5, cg = c & 31;
            *(float4*)&d_p[(((size_t)(b * G_ + g) * HW_) + pix) * CG_ + cg] = v;
        }
    }
}

// ---------------------------------------------------------------------------
// K2: 3x3 conv (128 -> 8 ch) + bias + tanh -> d_off (NCHW)
//     block: 16x32 output tile, 256 threads (16x16), 2 px/thread
// ---------------------------------------------------------------------------
__global__ __launch_bounds__(256, 2) void k2_conv3(const float* __restrict__ x,
                                                   const float* __restrict__ w_off,
                                                   const float* __restrict__ b_off) {
    __shared__ float ws[C_ * 9 * 8];   // [k][tap][oc], 36864B
    __shared__ float xt[18][34];       // input tile with halo

    int b = blockIdx.z;
    int h0 = blockIdx.y * 16;
    int w0 = blockIdx.x * 32;
    int tid = threadIdx.y * 16 + threadIdx.x;
    int tx = threadIdx.x;      // 0..15 -> col pair
    int ty = threadIdx.y;      // 0..15 -> row

    // load weights transposed: ws[(k*9+t)*8 + oc] = w_off[oc*1152 + k*9 + t]
    for (int idx = tid; idx < C_ * 9 * 8; idx += 256) {
        int k = idx / 72;
        int r = idx - k * 72;
        int t = r >> 3;
        int oc = r & 7;
        ws[idx] = w_off[oc * (C_ * 9) + k * 9 + t];
    }
    float bo[8];
#pragma unroll
    for (int oc = 0; oc < 8; oc++) bo[oc] = b_off[oc];
    __syncthreads();

    const float* xb = x + (size_t)b * C_ * HW_;
    float acc0[8], acc1[8];
#pragma unroll
    for (int oc = 0; oc < 8; oc++) { acc0[oc] = 0.f; acc1[oc] = 0.f; }

    for (int k = 0; k < C_; k++) {
        __syncthreads();
        // cooperative load of 18x34 tile with zero padding
        for (int idx = tid; idx < 18 * 34; idx += 256) {
            int r = idx / 34, cc = idx - r * 34;
            int h = h0 - 1 + r, w = w0 - 1 + cc;
            float v = 0.f;
            if (h >= 0 && h < H_ && w >= 0 && w < W_)
                v = xb[(size_t)k * HW_ + h * W_ + w];
            xt[r][cc] = v;
        }
        __syncthreads();

        float xv[3][4];
#pragma unroll
        for (int r = 0; r < 3; r++)
#pragma unroll
            for (int c = 0; c < 4; c++) xv[r][c] = xt[ty + r][2 * tx + c];

        const float* wk = &ws[k * 72];
#pragma unroll
        for (int t = 0; t < 9; t++) {
            int dy = t / 3, dx = t - dy * 3;
            float4 wA = *(const float4*)&wk[t * 8 + 0];
            float4 wB = *(const float4*)&wk[t * 8 + 4];
            float xv0 = xv[dy][dx];
            float xv1 = xv[dy][dx + 1];
            acc0[0] += xv0 * wA.x; acc0[1] += xv0 * wA.y; acc0[2] += xv0 * wA.z; acc0[3] += xv0 * wA.w;
            acc0[4] += xv0 * wB.x; acc0[5] += xv0 * wB.y; acc0[6] += xv0 * wB.z; acc0[7] += xv0 * wB.w;
            acc1[0] += xv1 * wA.x; acc1[1] += xv1 * wA.y; acc1[2] += xv1 * wA.z; acc1[3] += xv1 * wA.w;
            acc1[4] += xv1 * wB.x; acc1[5] += xv1 * wB.y; acc1[6] += xv1 * wB.z; acc1[7] += xv1 * wB.w;
        }
    }

    int y = h0 + ty;
    int xw = w0 + 2 * tx;
#pragma unroll
    for (int oc = 0; oc < 8; oc++) {
        float v0 = tanhf(acc0[oc] + bo[oc]);
        float v1 = tanhf(acc1[oc] + bo[oc]);
        size_t base = ((size_t)(b * 8 + oc) * H_ + y) * W_ + xw;
        d_off[base] = v0;
        d_off[base + 1] = v1;
    }
}

// ---------------------------------------------------------------------------
// K3: offset upsample + grid_sample(border, align_corners) + transposed store
//     block: 1024 thr = 32 warps; warp = one output pixel, lane = channel
//     grid: (ys*4+xt, g, b)
// ---------------------------------------------------------------------------
__global__ __launch_bounds__(1024) void k3_sample(float* __restrict__ out) {
    int bx = blockIdx.x;
    int ys = bx >> 2;
    int xt = bx & 3;
    int g = blockIdx.y;
    int b = blockIdx.z;
    int warp = threadIdx.x >> 5;
    int lane = threadIdx.x & 31;
    int xs = xt * 32 + warp;

    const float SY = 63.0f / 127.0f;     // (H-1)/(Hs-1)
    const float SO = 63.0f / 128.0f;     // (W-1)/2 * (2/max(Hs,Ws))

    // bilinear upsample (align_corners) of the two offset channels for group g
    float py = ys * SY;
    int y0u = (int)py;             // py >= 0
    float wyu = py - y0u;
    int y1u = min(y0u + 1, H_ - 1);
    float px = xs * SY;
    int x0u = (int)px;
    float wxu = px - x0u;
    int x1u = min(x0u + 1, W_ - 1);

    const float* offx = d_off + (size_t)(b * 8 + 2 * g) * HW_;
    const float* offy = offx + HW_;

    float a00 = offx[y0u * W_ + x0u], a01 = offx[y0u * W_ + x1u];
    float a10 = offx[y1u * W_ + x0u], a11 = offx[y1u * W_ + x1u];
    float o_x = (a00 * (1.f - wxu) + a01 * wxu) * (1.f - wyu)
              + (a10 * (1.f - wxu) + a11 * wxu) * wyu;

    float c00 = offy[y0u * W_ + x0u], c01 = offy[y0u * W_ + x1u];
    float c10 = offy[y1u * W_ + x0u], c11 = offy[y1u * W_ + x1u];
    float o_y = (c00 * (1.f - wxu) + c01 * wxu) * (1.f - wyu)
              + (c10 * (1.f - wxu) + c11 * wxu) * wyu;

    // sampling coords in input pixel space, border-clamped
    float ix = fminf(fmaxf(xs * SY + o_x * SO, 0.f), (float)(W_ - 1));
    float iy = fminf(fmaxf(ys * SY + o_y * SO, 0.f), (float)(H_ - 1));

    int ix0 = (int)ix; if (ix0 > W_ - 1) ix0 = W_ - 1;
    int iy0 = (int)iy; if (iy0 > H_ - 1) iy0 = H_ - 1;
    int ix1 = min(ix0 + 1, W_ - 1);
    int iy1 = min(iy0 + 1, H_ - 1);
    float fx = ix - ix0;
    float fy = iy - iy0;

    const float* pb = d_p + (size_t)(b * G_ + g) * HW_ * CG_;
    int r00 = (iy0 * W_ + ix0) * CG_;
    int r01 = (iy0 * W_ + ix1) * CG_;
    int r10 = (iy1 * W_ + ix0) * CG_;
    int r11 = (iy1 * W_ + ix1) * CG_;

    float v00 = pb[r00 + lane];
    float v01 = pb[r01 + lane];
    float v10 = pb[r10 + lane];
    float v11 = pb[r11 + lane];

    float res = (v00 * (1.f - fx) + v01 * fx) * (1.f - fy)
              + (v10 * (1.f - fx) + v11 * fx) * fy;

    // transpose in smem so stores are coalesced per channel
    __shared__ float tr[32][33];
    tr[warp][lane] = res;
    __syncthreads();

    float v = tr[lane][warp];   // pixel=lane, channel=warp
    out[(((size_t)(b * C_ + g * CG_ + warp)) * HS_ + ys) * WS_ + xt * 32 + lane] = v;
}

// ---------------------------------------------------------------------------
extern "C" void kernel_launch(void* const* d_in, const int* in_sizes, int n_in,
                              void* d_out, int out_size) {
    const float* x      = (const float*)d_in[0];
    const float* w_off  = (const float*)d_in[1];
    const float* b_off  = (const float*)d_in[2];
    const float* w_proj = (const float*)d_in[3];
    const float* gamma  = (const float*)d_in[4];
    const float* beta   = (const float*)d_in[5];
    const float* mean   = (const float*)d_in[6];
    const float* var    = (const float*)d_in[7];
    float* out = (float*)d_out;

    k0_prep<<<16, 1024>>>(w_proj, gamma, beta, mean, var);

    dim3 g1(HW_ / 128, B_);
    k1_gemm<<<g1, 256>>>(x);

    dim3 g2(W_ / 32, H_ / 16, B_);
    k2_conv3<<<g2, dim3(16, 16)>>>(x, w_off, b_off);

    dim3 g3(HS_ * 4, G_, B_);   // (ys,xt), g, b
    k3_sample<<<g3, 1024>>>(out);
}

// round 2
// speedup vs baseline: 1.6721x; 1.6721x over previous
#include <cuda_runtime.h>
#include <math.h>

// Problem constants (fixed shapes)
#define B_  16
#define C_  128
#define H_  64
#define W_  64
#define G_  4
#define CG_ 32
#define HW_ 4096      // H_*W_
#define HS_ 128
#define WS_ 128

// Scratch (static device globals; no runtime allocation)
__device__ float d_Wt[C_ * C_];           // Wt[k][c] = w_proj[c,k] * bn_scale[c]
__device__ float d_tb[C_];                // folded bias
__device__ float d_p[B_ * G_ * HW_ * CG_];// p in (b,g,pix,cg) layout, 33.5MB
__device__ float d_off[B_ * 8 * HW_];     // tanh offsets, NCHW (B,2G,H,W)

// ---------------------------------------------------------------------------
// K0: fold BN into transposed 1x1 weights + bias
// ---------------------------------------------------------------------------
__global__ void k0_prep(const float* __restrict__ w_proj,
                        const float* __restrict__ gamma,
                        const float* __restrict__ beta,
                        const float* __restrict__ mean,
                        const float* __restrict__ var) {
    int idx = blockIdx.x * blockDim.x + threadIdx.x;   // 16384 threads
    if (idx >= C_ * C_) return;
    int k = idx >> 7;
    int c = idx & 127;
    float s = gamma[c] / sqrtf(var[c] + 1e-5f);
    d_Wt[k * C_ + c] = w_proj[c * C_ + k] * s;
    if (idx < C_) {
        d_tb[idx] = beta[idx] - mean[idx] * (gamma[idx] / sqrtf(var[idx] + 1e-5f));
    }
}

// ---------------------------------------------------------------------------
// K1: 1x1 conv (GEMM M=pixels, N=128, K=128) + bias + SiLU
//     output layout: d_p[((b*G+g)*HW + pix)*32 + cg]
//     block: 128 pixels x 128 channels, 256 threads, 8x8 frags
// ---------------------------------------------------------------------------
__global__ __launch_bounds__(256, 2) void k1_gemm(const float* __restrict__ x) {
    int b = blockIdx.y;
    int pix0 = blockIdx.x * 128;
    __shared__ float As[16][128];   // k x pix
    __shared__ float Bs[16][132];   // k x c (padded)

    const float* xb = x + (size_t)b * C_ * HW_;
    int tid = threadIdx.x;
    int tx = tid & 15;              // pixel-frag group
    int ty = tid >> 4;              // channel-frag group
    int px0 = tx * 4;
    int cy0 = ty * 4;

    float acc[8][8];
#pragma unroll
    for (int i = 0; i < 8; i++)
#pragma unroll
        for (int j = 0; j < 8; j++) acc[i][j] = 0.f;

    for (int k0 = 0; k0 < C_; k0 += 16) {
        // load A tile: 16 x 128 = 512 float4
#pragma unroll
        for (int i = 0; i < 2; i++) {
            int idx = tid + i * 256;
            int kk = idx >> 5, pq = idx & 31;
            *(float4*)&As[kk][pq * 4] =
                *(const float4*)&xb[(size_t)(k0 + kk) * HW_ + pix0 + pq * 4];
        }
        // load B tile from pre-transposed Wt (coalesced)
#pragma unroll
        for (int i = 0; i < 2; i++) {
            int idx = tid + i * 256;
            int kk = idx >> 5, cq = idx & 31;
            *(float4*)&Bs[kk][cq * 4] =
                *(const float4*)&d_Wt[(k0 + kk) * C_ + cq * 4];
        }
        __syncthreads();
#pragma unroll
        for (int kk = 0; kk < 16; kk++) {
            float a[8], bb[8];
            *(float4*)&a[0] = *(float4*)&As[kk][px0];
            *(float4*)&a[4] = *(float4*)&As[kk][px0 + 64];
            *(float4*)&bb[0] = *(float4*)&Bs[kk][cy0];
            *(float4*)&bb[4] = *(float4*)&Bs[kk][cy0 + 64];
#pragma unroll
            for (int i = 0; i < 8; i++)
#pragma unroll
                for (int j = 0; j < 8; j++) acc[i][j] += a[i] * bb[j];
        }
        __syncthreads();
    }

    // epilogue: bias + SiLU, store to group-NHWC
    float tbv[8];
#pragma unroll
    for (int q = 0; q < 4; q++) { tbv[q] = d_tb[cy0 + q]; tbv[4 + q] = d_tb[cy0 + 64 + q]; }

#pragma unroll
    for (int i = 0; i < 8; i++) {
        int pix = pix0 + px0 + ((i < 4) ? i : 64 + (i - 4));
#pragma unroll
        for (int jh = 0; jh < 2; jh++) {
            int c = cy0 + jh * 64;
            float4 v;
            float u;
            u = acc[i][jh * 4 + 0] + tbv[jh * 4 + 0]; v.x = u * (1.f / (1.f + __expf(-u)));
            u = acc[i][jh * 4 + 1] + tbv[jh * 4 + 1]; v.y = u * (1.f / (1.f + __expf(-u)));
            u = acc[i][jh * 4 + 2] + tbv[jh * 4 + 2]; v.z = u * (1.f / (1.f + __expf(-u)));
            u = acc[i][jh * 4 + 3] + tbv[jh * 4 + 3]; v.w = u * (1.f / (1.f + __expf(-u)));
            int g = c >> 5, cg = c & 31;
            *(float4*)&d_p[(((size_t)(b * G_ + g) * HW_) + pix) * CG_ + cg] = v;
        }
    }
}

// ---------------------------------------------------------------------------
// K2: 3x3 conv (128 -> 8 ch) + bias + tanh -> d_off (NCHW)
//     block: 16x32 output tile, 256 threads (16x16), 2 px/thread
//     Double-buffered input tiles: one __syncthreads per channel.
// ---------------------------------------------------------------------------
__global__ __launch_bounds__(256, 2) void k2_conv3(const float* __restrict__ x,
                                                   const float* __restrict__ w_off,
                                                   const float* __restrict__ b_off) {
    __shared__ float ws[C_ * 9 * 8];      // [k][tap][oc], 36864B
    __shared__ float xt2[2][18 * 34];     // double-buffered input tile

    int b = blockIdx.z;
    int h0 = blockIdx.y * 16;
    int w0 = blockIdx.x * 32;
    int tid = threadIdx.y * 16 + threadIdx.x;
    int tx = threadIdx.x;      // 0..15 -> col pair
    int ty = threadIdx.y;      // 0..15 -> row

    // load weights transposed: ws[(k*9+t)*8 + oc] = w_off[oc*1152 + k*9 + t]
    for (int idx = tid; idx < C_ * 9 * 8; idx += 256) {
        int k = idx / 72;
        int r = idx - k * 72;
        int t = r >> 3;
        int oc = r & 7;
        ws[idx] = w_off[oc * (C_ * 9) + k * 9 + t];
    }
    float bo[8];
#pragma unroll
    for (int oc = 0; oc < 8; oc++) bo[oc] = b_off[oc];

    const float* xb = x + (size_t)b * C_ * HW_;

    // precompute this thread's 3 tile-slot coordinates (fixed across k)
    int sidx[3], sh[3], sw[3];
    bool sval[3];
#pragma unroll
    for (int i = 0; i < 3; i++) {
        int idx = tid + i * 256;
        sidx[i] = idx;
        int r = idx / 34, cc = idx - r * 34;
        sh[i] = h0 - 1 + r;
        sw[i] = w0 - 1 + cc;
        sval[i] = (idx < 612) && (sh[i] >= 0) && (sh[i] < H_) && (sw[i] >= 0) && (sw[i] < W_);
    }

    // prefetch k=0 tile into buffer 0
#pragma unroll
    for (int i = 0; i < 3; i++) {
        if (sidx[i] < 612) {
            float v = sval[i] ? xb[sh[i] * W_ + sw[i]] : 0.f;
            xt2[0][sidx[i]] = v;
        }
    }
    __syncthreads();

    float acc0[8], acc1[8];
#pragma unroll
    for (int oc = 0; oc < 8; oc++) { acc0[oc] = 0.f; acc1[oc] = 0.f; }

    for (int k = 0; k < C_; k++) {
        int cur = k & 1;

        // issue prefetch loads for channel k+1 (LDGs overlap the FMA chain)
        float pf[3] = {0.f, 0.f, 0.f};
        if (k + 1 < C_) {
            const float* xk = xb + (size_t)(k + 1) * HW_;
#pragma unroll
            for (int i = 0; i < 3; i++)
                if (sval[i]) pf[i] = xk[sh[i] * W_ + sw[i]];
        }

        const float* xtc = &xt2[cur][0];
        float xv[3][4];
#pragma unroll
        for (int r = 0; r < 3; r++)
#pragma unroll
            for (int c = 0; c < 4; c++) xv[r][c] = xtc[(ty + r) * 34 + 2 * tx + c];

        const float* wk = &ws[k * 72];
#pragma unroll
        for (int t = 0; t < 9; t++) {
            int dy = t / 3, dx = t - dy * 3;
            float4 wA = *(const float4*)&wk[t * 8 + 0];
            float4 wB = *(const float4*)&wk[t * 8 + 4];
            float xv0 = xv[dy][dx];
            float xv1 = xv[dy][dx + 1];
            acc0[0] += xv0 * wA.x; acc0[1] += xv0 * wA.y; acc0[2] += xv0 * wA.z; acc0[3] += xv0 * wA.w;
            acc0[4] += xv0 * wB.x; acc0[5] += xv0 * wB.y; acc0[6] += xv0 * wB.z; acc0[7] += xv0 * wB.w;
            acc1[0] += xv1 * wA.x; acc1[1] += xv1 * wA.y; acc1[2] += xv1 * wA.z; acc1[3] += xv1 * wA.w;
            acc1[4] += xv1 * wB.x; acc1[5] += xv1 * wB.y; acc1[6] += xv1 * wB.z; acc1[7] += xv1 * wB.w;
        }

        // commit prefetch to the other buffer
        if (k + 1 < C_) {
            int nb = cur ^ 1;
#pragma unroll
            for (int i = 0; i < 3; i++)
                if (sidx[i] < 612) xt2[nb][sidx[i]] = pf[i];
        }
        __syncthreads();
    }

    int y = h0 + ty;
    int xw = w0 + 2 * tx;
#pragma unroll
    for (int oc = 0; oc < 8; oc++) {
        float v0 = tanhf(acc0[oc] + bo[oc]);
        float v1 = tanhf(acc1[oc] + bo[oc]);
        size_t base = ((size_t)(b * 8 + oc) * H_ + y) * W_ + xw;
        d_off[base] = v0;
        d_off[base + 1] = v1;
    }
}

// ---------------------------------------------------------------------------
// K3: offset upsample + grid_sample(border, align_corners) + transposed store
//     Two-phase: phase A computes per-pixel coords ONCE (128 px/block),
//     phase B: warp = channel-vector sampler, 4 pixels per warp.
//     block: 1024 thr = 32 warps; grid: ((HS/4)*(WS/32)=128, G, B)
// ---------------------------------------------------------------------------
__global__ __launch_bounds__(1024) void k3_sample(float* __restrict__ out) {
    int bx = blockIdx.x;
    int ys0 = (bx >> 2) * 4;       // 4 output rows per block
    int xs0 = (bx & 3) * 32;       // 32 output cols per block
    int g = blockIdx.y;
    int b = blockIdx.z;
    int tid = threadIdx.x;
    int warp = tid >> 5;
    int lane = tid & 31;

    __shared__ int   s_r[4][32][4];    // corner base offsets (already *CG_)
    __shared__ float s_f[4][32][2];    // fx, fy
    __shared__ float tr[4][32][33];    // transpose buffers (one per row)

    // ---- Phase A: one thread per output pixel computes sampling coords ----
    if (tid < 128) {
        int r = tid >> 5;
        int xl = tid & 31;
        int ys = ys0 + r;
        int xs = xs0 + xl;

        const float SY = 63.0f / 127.0f;     // (H-1)/(Hs-1)
        const float SO = 63.0f / 128.0f;     // (W-1)/2 * (2/max(Hs,Ws))

        float py = ys * SY;
        int y0u = (int)py;
        float wyu = py - y0u;
        int y1u = min(y0u + 1, H_ - 1);
        float px = xs * SY;
        int x0u = (int)px;
        float wxu = px - x0u;
        int x1u = min(x0u + 1, W_ - 1);

        const float* offx = d_off + (size_t)(b * 8 + 2 * g) * HW_;
        const float* offy = offx + HW_;

        float a00 = offx[y0u * W_ + x0u], a01 = offx[y0u * W_ + x1u];
        float a10 = offx[y1u * W_ + x0u], a11 = offx[y1u * W_ + x1u];
        float o_x = (a00 * (1.f - wxu) + a01 * wxu) * (1.f - wyu)
                  + (a10 * (1.f - wxu) + a11 * wxu) * wyu;

        float c00 = offy[y0u * W_ + x0u], c01 = offy[y0u * W_ + x1u];
        float c10 = offy[y1u * W_ + x0u], c11 = offy[y1u * W_ + x1u];
        float o_y = (c00 * (1.f - wxu) + c01 * wxu) * (1.f - wyu)
                  + (c10 * (1.f - wxu) + c11 * wxu) * wyu;

        float ix = fminf(fmaxf(xs * SY + o_x * SO, 0.f), (float)(W_ - 1));
        float iy = fminf(fmaxf(ys * SY + o_y * SO, 0.f), (float)(H_ - 1));

        int ix0 = (int)ix; if (ix0 > W_ - 1) ix0 = W_ - 1;
        int iy0 = (int)iy; if (iy0 > H_ - 1) iy0 = H_ - 1;
        int ix1 = min(ix0 + 1, W_ - 1);
        int iy1 = min(iy0 + 1, H_ - 1);

        s_r[r][xl][0] = (iy0 * W_ + ix0) * CG_;
        s_r[r][xl][1] = (iy0 * W_ + ix1) * CG_;
        s_r[r][xl][2] = (iy1 * W_ + ix0) * CG_;
        s_r[r][xl][3] = (iy1 * W_ + ix1) * CG_;
        s_f[r][xl][0] = ix - ix0;
        s_f[r][xl][1] = iy - iy0;
    }
    __syncthreads();

    // ---- Phase B: warp w samples pixel (r, xs0+w) for all 32 channels ----
    const float* pb = d_p + (size_t)(b * G_ + g) * HW_ * CG_;
#pragma unroll
    for (int r = 0; r < 4; r++) {
        int r00 = s_r[r][warp][0];
        int r01 = s_r[r][warp][1];
        int r10 = s_r[r][warp][2];
        int r11 = s_r[r][warp][3];
        float fx = s_f[r][warp][0];
        float fy = s_f[r][warp][1];

        float v00 = pb[r00 + lane];
        float v01 = pb[r01 + lane];
        float v10 = pb[r10 + lane];
        float v11 = pb[r11 + lane];

        tr[r][warp][lane] = (v00 * (1.f - fx) + v01 * fx) * (1.f - fy)
                          + (v10 * (1.f - fx) + v11 * fx) * fy;
    }
    __syncthreads();

    // ---- coalesced store: warp w owns channel w, writes 4 rows of 32 px ----
    size_t obase = ((size_t)(b * C_ + g * CG_ + warp)) * HS_ * WS_;
#pragma unroll
    for (int r = 0; r < 4; r++) {
        out[obase + (size_t)(ys0 + r) * WS_ + xs0 + lane] = tr[r][lane][warp];
    }
}

// ---------------------------------------------------------------------------
extern "C" void kernel_launch(void* const* d_in, const int* in_sizes, int n_in,
                              void* d_out, int out_size) {
    const float* x      = (const float*)d_in[0];
    const float* w_off  = (const float*)d_in[1];
    const float* b_off  = (const float*)d_in[2];
    const float* w_proj = (const float*)d_in[3];
    const float* gamma  = (const float*)d_in[4];
    const float* beta   = (const float*)d_in[5];
    const float* mean   = (const float*)d_in[6];
    const float* var    = (const float*)d_in[7];
    float* out = (float*)d_out;

    k0_prep<<<16, 1024>>>(w_proj, gamma, beta, mean, var);

    dim3 g1(HW_ / 128, B_);
    k1_gemm<<<g1, 256>>>(x);

    dim3 g2(W_ / 32, H_ / 16, B_);
    k2_conv3<<<g2, dim3(16, 16)>>>(x, w_off, b_off);

    dim3 g3((HS_ / 4) * (WS_ / 32), G_, B_);
    k3_sample<<<g3, 1024>>>(out);
}

// round 3
// speedup vs baseline: 1.7545x; 1.0493x over previous
#include <cuda_runtime.h>
#include <math.h>

// Problem constants (fixed shapes)
#define B_  16
#define C_  128
#define H_  64
#define W_  64
#define G_  4
#define CG_ 32
#define HW_ 4096      // H_*W_
#define HS_ 128
#define WS_ 128

// Scratch (static device globals; no runtime allocation)
__device__ float d_Wt[C_ * C_];           // Wt[k][c] = w_proj[c,k] * bn_scale[c]
__device__ float d_tb[C_];                // folded bias
__device__ float d_p[B_ * G_ * HW_ * CG_];// p in (b,g,pix,cg) layout, 33.5MB
__device__ float d_off[B_ * 8 * HW_];     // tanh offsets, NCHW (B,2G,H,W)

// ---- packed fp32x2 helpers (Blackwell FFMA2 / FMUL2) ----
__device__ __forceinline__ float2 fma2(float2 a, float2 b, float2 c) {
    float2 d;
    asm("fma.rn.f32x2 %0, %1, %2, %3;"
        : "=l"(reinterpret_cast<unsigned long long&>(d))
        : "l"(reinterpret_cast<unsigned long long&>(a)),
          "l"(reinterpret_cast<unsigned long long&>(b)),
          "l"(reinterpret_cast<unsigned long long&>(c)));
    return d;
}
__device__ __forceinline__ float2 mul2(float2 a, float2 b) {
    float2 d;
    asm("mul.rn.f32x2 %0, %1, %2;"
        : "=l"(reinterpret_cast<unsigned long long&>(d))
        : "l"(reinterpret_cast<unsigned long long&>(a)),
          "l"(reinterpret_cast<unsigned long long&>(b)));
    return d;
}

// ---------------------------------------------------------------------------
// K0: fold BN into transposed 1x1 weights + bias
// ---------------------------------------------------------------------------
__global__ void k0_prep(const float* __restrict__ w_proj,
                        const float* __restrict__ gamma,
                        const float* __restrict__ beta,
                        const float* __restrict__ mean,
                        const float* __restrict__ var) {
    int idx = blockIdx.x * blockDim.x + threadIdx.x;
    if (idx >= C_ * C_) return;
    int k = idx >> 7;
    int c = idx & 127;
    float s = gamma[c] / sqrtf(var[c] + 1e-5f);
    d_Wt[k * C_ + c] = w_proj[c * C_ + k] * s;
    if (idx < C_) {
        d_tb[idx] = beta[idx] - mean[idx] * (gamma[idx] / sqrtf(var[idx] + 1e-5f));
    }
}

// ---------------------------------------------------------------------------
// K1: 1x1 conv (GEMM M=pixels, N=128, K=128) + bias + SiLU, FFMA2 inner loop
//     output layout: d_p[((b*G+g)*HW + pix)*32 + cg]
// ---------------------------------------------------------------------------
__global__ __launch_bounds__(256, 2) void k1_gemm(const float* __restrict__ x) {
    int b = blockIdx.y;
    int pix0 = blockIdx.x * 128;
    __shared__ float As[16][128];   // k x pix
    __shared__ float Bs[16][132];   // k x c (padded)

    const float* xb = x + (size_t)b * C_ * HW_;
    int tid = threadIdx.x;
    int tx = tid & 15;              // pixel-frag group
    int ty = tid >> 4;              // channel-frag group
    int px0 = tx * 4;
    int cy0 = ty * 4;

    float2 acc[8][4];               // [pixel][channel-pair]
#pragma unroll
    for (int i = 0; i < 8; i++)
#pragma unroll
        for (int j = 0; j < 4; j++) acc[i][j] = make_float2(0.f, 0.f);

    for (int k0 = 0; k0 < C_; k0 += 16) {
#pragma unroll
        for (int i = 0; i < 2; i++) {
            int idx = tid + i * 256;
            int kk = idx >> 5, pq = idx & 31;
            *(float4*)&As[kk][pq * 4] =
                *(const float4*)&xb[(size_t)(k0 + kk) * HW_ + pix0 + pq * 4];
        }
#pragma unroll
        for (int i = 0; i < 2; i++) {
            int idx = tid + i * 256;
            int kk = idx >> 5, cq = idx & 31;
            *(float4*)&Bs[kk][cq * 4] =
                *(const float4*)&d_Wt[(k0 + kk) * C_ + cq * 4];
        }
        __syncthreads();
#pragma unroll
        for (int kk = 0; kk < 16; kk++) {
            float a[8];
            float2 bp[4];
            *(float4*)&a[0] = *(float4*)&As[kk][px0];
            *(float4*)&a[4] = *(float4*)&As[kk][px0 + 64];
            *(float4*)&bp[0] = *(float4*)&Bs[kk][cy0];
            *(float4*)&bp[2] = *(float4*)&Bs[kk][cy0 + 64];
#pragma unroll
            for (int i = 0; i < 8; i++) {
                float2 ai = make_float2(a[i], a[i]);
#pragma unroll
                for (int j = 0; j < 4; j++)
                    acc[i][j] = fma2(ai, bp[j], acc[i][j]);
            }
        }
        __syncthreads();
    }

    // epilogue: bias + SiLU, store to group-NHWC
    float tbv[8];
#pragma unroll
    for (int q = 0; q < 4; q++) { tbv[q] = d_tb[cy0 + q]; tbv[4 + q] = d_tb[cy0 + 64 + q]; }

#pragma unroll
    for (int i = 0; i < 8; i++) {
        int pix = pix0 + px0 + ((i < 4) ? i : 64 + (i - 4));
#pragma unroll
        for (int jh = 0; jh < 2; jh++) {
            int c = cy0 + jh * 64;
            float av[4] = { acc[i][jh * 2].x, acc[i][jh * 2].y,
                            acc[i][jh * 2 + 1].x, acc[i][jh * 2 + 1].y };
            float4 v;
            float u;
            u = av[0] + tbv[jh * 4 + 0]; v.x = u * (1.f / (1.f + __expf(-u)));
            u = av[1] + tbv[jh * 4 + 1]; v.y = u * (1.f / (1.f + __expf(-u)));
            u = av[2] + tbv[jh * 4 + 2]; v.z = u * (1.f / (1.f + __expf(-u)));
            u = av[3] + tbv[jh * 4 + 3]; v.w = u * (1.f / (1.f + __expf(-u)));
            int g = c >> 5, cg = c & 31;
            *(float4*)&d_p[(((size_t)(b * G_ + g) * HW_) + pix) * CG_ + cg] = v;
        }
    }
}

// ---------------------------------------------------------------------------
// K2: 3x3 conv (128 -> 8 ch) + bias + tanh -> d_off (NCHW), FFMA2 inner loop
//     block: 16x32 output tile, 256 threads (16x16), 2 px/thread
// ---------------------------------------------------------------------------
__global__ __launch_bounds__(256, 2) void k2_conv3(const float* __restrict__ x,
                                                   const float* __restrict__ w_off,
                                                   const float* __restrict__ b_off) {
    __shared__ float ws[C_ * 9 * 8];      // [k][tap][oc], 36864B
    __shared__ float xt2[2][18 * 34];     // double-buffered input tile

    int b = blockIdx.z;
    int h0 = blockIdx.y * 16;
    int w0 = blockIdx.x * 32;
    int tid = threadIdx.y * 16 + threadIdx.x;
    int tx = threadIdx.x;
    int ty = threadIdx.y;

    for (int idx = tid; idx < C_ * 9 * 8; idx += 256) {
        int k = idx / 72;
        int r = idx - k * 72;
        int t = r >> 3;
        int oc = r & 7;
        ws[idx] = w_off[oc * (C_ * 9) + k * 9 + t];
    }
    float bo[8];
#pragma unroll
    for (int oc = 0; oc < 8; oc++) bo[oc] = b_off[oc];

    const float* xb = x + (size_t)b * C_ * HW_;

    int sidx[3], sh[3], sw[3];
    bool sval[3];
#pragma unroll
    for (int i = 0; i < 3; i++) {
        int idx = tid + i * 256;
        sidx[i] = idx;
        int r = idx / 34, cc = idx - r * 34;
        sh[i] = h0 - 1 + r;
        sw[i] = w0 - 1 + cc;
        sval[i] = (idx < 612) && (sh[i] >= 0) && (sh[i] < H_) && (sw[i] >= 0) && (sw[i] < W_);
    }

#pragma unroll
    for (int i = 0; i < 3; i++) {
        if (sidx[i] < 612) {
            float v = sval[i] ? xb[sh[i] * W_ + sw[i]] : 0.f;
            xt2[0][sidx[i]] = v;
        }
    }
    __syncthreads();

    float2 acc0[4], acc1[4];      // packed over oc pairs
#pragma unroll
    for (int q = 0; q < 4; q++) { acc0[q] = make_float2(0.f, 0.f); acc1[q] = make_float2(0.f, 0.f); }

    for (int k = 0; k < C_; k++) {
        int cur = k & 1;

        float pf[3] = {0.f, 0.f, 0.f};
        if (k + 1 < C_) {
            const float* xk = xb + (size_t)(k + 1) * HW_;
#pragma unroll
            for (int i = 0; i < 3; i++)
                if (sval[i]) pf[i] = xk[sh[i] * W_ + sw[i]];
        }

        const float* xtc = &xt2[cur][0];
        float xv[3][4];
#pragma unroll
        for (int r = 0; r < 3; r++)
#pragma unroll
            for (int c = 0; c < 4; c++) xv[r][c] = xtc[(ty + r) * 34 + 2 * tx + c];

        const float* wk = &ws[k * 72];
#pragma unroll
        for (int t = 0; t < 9; t++) {
            int dy = t / 3, dx = t - dy * 3;
            float2 wp[4];
            *(float4*)&wp[0] = *(const float4*)&wk[t * 8 + 0];
            *(float4*)&wp[2] = *(const float4*)&wk[t * 8 + 4];
            float2 xp0 = make_float2(xv[dy][dx], xv[dy][dx]);
            float2 xp1 = make_float2(xv[dy][dx + 1], xv[dy][dx + 1]);
#pragma unroll
            for (int q = 0; q < 4; q++) {
                acc0[q] = fma2(xp0, wp[q], acc0[q]);
                acc1[q] = fma2(xp1, wp[q], acc1[q]);
            }
        }

        if (k + 1 < C_) {
            int nb = cur ^ 1;
#pragma unroll
            for (int i = 0; i < 3; i++)
                if (sidx[i] < 612) xt2[nb][sidx[i]] = pf[i];
        }
        __syncthreads();
    }

    int y = h0 + ty;
    int xw = w0 + 2 * tx;
#pragma unroll
    for (int q = 0; q < 4; q++) {
        float a0[2] = { acc0[q].x, acc0[q].y };
        float a1[2] = { acc1[q].x, acc1[q].y };
#pragma unroll
        for (int h = 0; h < 2; h++) {
            int oc = q * 2 + h;
            float v0 = tanhf(a0[h] + bo[oc]);
            float v1 = tanhf(a1[h] + bo[oc]);
            size_t base = ((size_t)(b * 8 + oc) * H_ + y) * W_ + xw;
            d_off[base] = v0;
            d_off[base + 1] = v1;
        }
    }
}

// ---------------------------------------------------------------------------
// K3: offset upsample + grid_sample(border, align_corners) + transposed store
//     Phase A: 128 threads compute per-pixel coords once.
//     Phase B: half-warp = one pixel, lane pair-loads 2 channels (float2),
//              packed-f32x2 lerp. 2 iterations cover 128 px/block.
// ---------------------------------------------------------------------------
__global__ __launch_bounds__(1024) void k3_sample(float* __restrict__ out) {
    int bx = blockIdx.x;
    int ys0 = (bx >> 2) * 4;       // 4 output rows per block
    int xs0 = (bx & 3) * 32;       // 32 output cols per block
    int g = blockIdx.y;
    int b = blockIdx.z;
    int tid = threadIdx.x;
    int warp = tid >> 5;
    int lane = tid & 31;

    __shared__ int   s_r[4][32][4];    // corner base offsets (already *CG_)
    __shared__ float s_f[4][32][2];    // fx, fy
    __shared__ float tr[4][32][33];    // transpose buffers

    // ---- Phase A ----
    if (tid < 128) {
        int r = tid >> 5;
        int xl = tid & 31;
        int ys = ys0 + r;
        int xs = xs0 + xl;

        const float SY = 63.0f / 127.0f;
        const float SO = 63.0f / 128.0f;

        float py = ys * SY;
        int y0u = (int)py;
        float wyu = py - y0u;
        int y1u = min(y0u + 1, H_ - 1);
        float px = xs * SY;
        int x0u = (int)px;
        float wxu = px - x0u;
        int x1u = min(x0u + 1, W_ - 1);

        const float* offx = d_off + (size_t)(b * 8 + 2 * g) * HW_;
        const float* offy = offx + HW_;

        float a00 = offx[y0u * W_ + x0u], a01 = offx[y0u * W_ + x1u];
        float a10 = offx[y1u * W_ + x0u], a11 = offx[y1u * W_ + x1u];
        float o_x = (a00 * (1.f - wxu) + a01 * wxu) * (1.f - wyu)
                  + (a10 * (1.f - wxu) + a11 * wxu) * wyu;

        float c00 = offy[y0u * W_ + x0u], c01 = offy[y0u * W_ + x1u];
        float c10 = offy[y1u * W_ + x0u], c11 = offy[y1u * W_ + x1u];
        float o_y = (c00 * (1.f - wxu) + c01 * wxu) * (1.f - wyu)
                  + (c10 * (1.f - wxu) + c11 * wxu) * wyu;

        float ix = fminf(fmaxf(xs * SY + o_x * SO, 0.f), (float)(W_ - 1));
        float iy = fminf(fmaxf(ys * SY + o_y * SO, 0.f), (float)(H_ - 1));

        int ix0 = (int)ix; if (ix0 > W_ - 1) ix0 = W_ - 1;
        int iy0 = (int)iy; if (iy0 > H_ - 1) iy0 = H_ - 1;
        int ix1 = min(ix0 + 1, W_ - 1);
        int iy1 = min(iy0 + 1, H_ - 1);

        s_r[r][xl][0] = (iy0 * W_ + ix0) * CG_;
        s_r[r][xl][1] = (iy0 * W_ + ix1) * CG_;
        s_r[r][xl][2] = (iy1 * W_ + ix0) * CG_;
        s_r[r][xl][3] = (iy1 * W_ + ix1) * CG_;
        s_f[r][xl][0] = ix - ix0;
        s_f[r][xl][1] = iy - iy0;
    }
    __syncthreads();

    // ---- Phase B: half-warp = pixel, lane handles 2 channels ----
    const float2* pb2 = (const float2*)(d_p + (size_t)(b * G_ + g) * HW_ * CG_);
    int half = lane >> 4;          // 0/1
    int l16 = lane & 15;           // channel-pair index
#pragma unroll
    for (int it = 0; it < 2; it++) {
        int pix = warp * 2 + half + it * 64;   // 0..127
        int r = pix >> 5, cc = pix & 31;

        int r00 = s_r[r][cc][0] >> 1;
        int r01 = s_r[r][cc][1] >> 1;
        int r10 = s_r[r][cc][2] >> 1;
        int r11 = s_r[r][cc][3] >> 1;
        float fx = s_f[r][cc][0];
        float fy = s_f[r][cc][1];

        float2 v00 = pb2[r00 + l16];
        float2 v01 = pb2[r01 + l16];
        float2 v10 = pb2[r10 + l16];
        float2 v11 = pb2[r11 + l16];

        float2 fx2  = make_float2(fx, fx);
        float2 ofx2 = make_float2(1.f - fx, 1.f - fx);
        float2 fy2  = make_float2(fy, fy);
        float2 ofy2 = make_float2(1.f - fy, 1.f - fy);

        float2 t0 = fma2(v00, ofx2, mul2(v01, fx2));
        float2 t1 = fma2(v10, ofx2, mul2(v11, fx2));
        float2 res = fma2(t0, ofy2, mul2(t1, fy2));

        tr[r][cc][2 * l16]     = res.x;
        tr[r][cc][2 * l16 + 1] = res.y;
    }
    __syncthreads();

    // ---- coalesced store: warp w owns channel w, writes 4 rows of 32 px ----
    size_t obase = ((size_t)(b * C_ + g * CG_ + warp)) * HS_ * WS_;
#pragma unroll
    for (int r = 0; r < 4; r++) {
        out[obase + (size_t)(ys0 + r) * WS_ + xs0 + lane] = tr[r][lane][warp];
    }
}

// ---------------------------------------------------------------------------
extern "C" void kernel_launch(void* const* d_in, const int* in_sizes, int n_in,
                              void* d_out, int out_size) {
    const float* x      = (const float*)d_in[0];
    const float* w_off  = (const float*)d_in[1];
    const float* b_off  = (const float*)d_in[2];
    const float* w_proj = (const float*)d_in[3];
    const float* gamma  = (const float*)d_in[4];
    const float* beta   = (const float*)d_in[5];
    const float* mean   = (const float*)d_in[6];
    const float* var    = (const float*)d_in[7];
    float* out = (float*)d_out;

    k0_prep<<<16, 1024>>>(w_proj, gamma, beta, mean, var);

    dim3 g1(HW_ / 128, B_);
    k1_gemm<<<g1, 256>>>(x);

    dim3 g2(W_ / 32, H_ / 16, B_);
    k2_conv3<<<g2, dim3(16, 16)>>>(x, w_off, b_off);

    dim3 g3((HS_ / 4) * (WS_ / 32), G_, B_);
    k3_sample<<<g3, 1024>>>(out);
}

// round 4
// speedup vs baseline: 2.0086x; 1.1448x over previous
#include <cuda_runtime.h>
#include <math.h>

// Problem constants (fixed shapes)
#define B_  16
#define C_  128
#define H_  64
#define W_  64
#define G_  4
#define CG_ 32
#define HW_ 4096      // H_*W_
#define HS_ 128
#define WS_ 128

// Scratch (static device globals; no runtime allocation)
__device__ float d_Wt[C_ * C_];            // Wt[k][c] = w_proj[c,k] * bn_scale[c]
__device__ float d_tb[C_];                 // folded bias
__device__ float d_p[B_ * G_ * HW_ * CG_]; // p in (b,g,pix,cg) layout, 33.5MB
__device__ float d_off[B_ * 8 * HW_];      // tanh offsets, NCHW (B,2G,H,W)
__device__ float d_part[4 * B_ * 8 * HW_]; // K2 k-split partial sums, 8MB

// ---- packed fp32x2 helpers (Blackwell FFMA2 / FMUL2) ----
__device__ __forceinline__ float2 fma2(float2 a, float2 b, float2 c) {
    float2 d;
    asm("fma.rn.f32x2 %0, %1, %2, %3;"
        : "=l"(reinterpret_cast<unsigned long long&>(d))
        : "l"(reinterpret_cast<unsigned long long&>(a)),
          "l"(reinterpret_cast<unsigned long long&>(b)),
          "l"(reinterpret_cast<unsigned long long&>(c)));
    return d;
}
__device__ __forceinline__ float2 mul2(float2 a, float2 b) {
    float2 d;
    asm("mul.rn.f32x2 %0, %1, %2;"
        : "=l"(reinterpret_cast<unsigned long long&>(d))
        : "l"(reinterpret_cast<unsigned long long&>(a)),
          "l"(reinterpret_cast<unsigned long long&>(b)));
    return d;
}

// ---------------------------------------------------------------------------
// K0: fold BN into transposed 1x1 weights + bias
// ---------------------------------------------------------------------------
__global__ void k0_prep(const float* __restrict__ w_proj,
                        const float* __restrict__ gamma,
                        const float* __restrict__ beta,
                        const float* __restrict__ mean,
                        const float* __restrict__ var) {
    int idx = blockIdx.x * blockDim.x + threadIdx.x;
    if (idx >= C_ * C_) return;
    int k = idx >> 7;
    int c = idx & 127;
    float s = gamma[c] / sqrtf(var[c] + 1e-5f);
    d_Wt[k * C_ + c] = w_proj[c * C_ + k] * s;
    if (idx < C_) {
        d_tb[idx] = beta[idx] - mean[idx] * (gamma[idx] / sqrtf(var[idx] + 1e-5f));
    }
}

// ---------------------------------------------------------------------------
// K1: 1x1 conv (GEMM M=pixels, N=128, K=128) + bias + SiLU, FFMA2 inner loop
// ---------------------------------------------------------------------------
__global__ __launch_bounds__(256, 2) void k1_gemm(const float* __restrict__ x) {
    int b = blockIdx.y;
    int pix0 = blockIdx.x * 128;
    __shared__ float As[16][128];
    __shared__ float Bs[16][132];

    const float* xb = x + (size_t)b * C_ * HW_;
    int tid = threadIdx.x;
    int tx = tid & 15;
    int ty = tid >> 4;
    int px0 = tx * 4;
    int cy0 = ty * 4;

    float2 acc[8][4];
#pragma unroll
    for (int i = 0; i < 8; i++)
#pragma unroll
        for (int j = 0; j < 4; j++) acc[i][j] = make_float2(0.f, 0.f);

    for (int k0 = 0; k0 < C_; k0 += 16) {
#pragma unroll
        for (int i = 0; i < 2; i++) {
            int idx = tid + i * 256;
            int kk = idx >> 5, pq = idx & 31;
            *(float4*)&As[kk][pq * 4] =
                *(const float4*)&xb[(size_t)(k0 + kk) * HW_ + pix0 + pq * 4];
        }
#pragma unroll
        for (int i = 0; i < 2; i++) {
            int idx = tid + i * 256;
            int kk = idx >> 5, cq = idx & 31;
            *(float4*)&Bs[kk][cq * 4] =
                *(const float4*)&d_Wt[(k0 + kk) * C_ + cq * 4];
        }
        __syncthreads();
#pragma unroll
        for (int kk = 0; kk < 16; kk++) {
            float a[8];
            float2 bp[4];
            *(float4*)&a[0] = *(float4*)&As[kk][px0];
            *(float4*)&a[4] = *(float4*)&As[kk][px0 + 64];
            *(float4*)&bp[0] = *(float4*)&Bs[kk][cy0];
            *(float4*)&bp[2] = *(float4*)&Bs[kk][cy0 + 64];
#pragma unroll
            for (int i = 0; i < 8; i++) {
                float2 ai = make_float2(a[i], a[i]);
#pragma unroll
                for (int j = 0; j < 4; j++)
                    acc[i][j] = fma2(ai, bp[j], acc[i][j]);
            }
        }
        __syncthreads();
    }

    float tbv[8];
#pragma unroll
    for (int q = 0; q < 4; q++) { tbv[q] = d_tb[cy0 + q]; tbv[4 + q] = d_tb[cy0 + 64 + q]; }

#pragma unroll
    for (int i = 0; i < 8; i++) {
        int pix = pix0 + px0 + ((i < 4) ? i : 64 + (i - 4));
#pragma unroll
        for (int jh = 0; jh < 2; jh++) {
            int c = cy0 + jh * 64;
            float av[4] = { acc[i][jh * 2].x, acc[i][jh * 2].y,
                            acc[i][jh * 2 + 1].x, acc[i][jh * 2 + 1].y };
            float4 v;
            float u;
            u = av[0] + tbv[jh * 4 + 0]; v.x = u * (1.f / (1.f + __expf(-u)));
            u = av[1] + tbv[jh * 4 + 1]; v.y = u * (1.f / (1.f + __expf(-u)));
            u = av[2] + tbv[jh * 4 + 2]; v.z = u * (1.f / (1.f + __expf(-u)));
            u = av[3] + tbv[jh * 4 + 3]; v.w = u * (1.f / (1.f + __expf(-u)));
            int g = c >> 5, cg = c & 31;
            *(float4*)&d_p[(((size_t)(b * G_ + g) * HW_) + pix) * CG_ + cg] = v;
        }
    }
}

// ---------------------------------------------------------------------------
// K2a: 3x3 conv partials over a 32-channel k-slice (4-way k-split)
//      grid: (W/32, H/16, B*4). blockIdx.z = b*4 + split.
//      Writes d_part[((split*B+b)*8+oc)*HW + pix]  (no bias/tanh yet)
// ---------------------------------------------------------------------------
__global__ __launch_bounds__(256, 4) void k2a_conv3(const float* __restrict__ x,
                                                    const float* __restrict__ w_off) {
    __shared__ float ws[32 * 9 * 8];      // this slice's weights, 9216B
    __shared__ float xt2[2][18 * 34];     // double-buffered input tile

    int bz = blockIdx.z;
    int b = bz >> 2;
    int split = bz & 3;
    int k_lo = split * 32;
    int h0 = blockIdx.y * 16;
    int w0 = blockIdx.x * 32;
    int tid = threadIdx.y * 16 + threadIdx.x;
    int tx = threadIdx.x;
    int ty = threadIdx.y;

    // weights transposed: ws[(kk*9+t)*8 + oc] = w_off[oc*1152 + (k_lo+kk)*9 + t]
    for (int idx = tid; idx < 32 * 9 * 8; idx += 256) {
        int kk = idx / 72;
        int r = idx - kk * 72;
        int t = r >> 3;
        int oc = r & 7;
        ws[idx] = w_off[oc * (C_ * 9) + (k_lo + kk) * 9 + t];
    }

    const float* xb = x + (size_t)b * C_ * HW_ + (size_t)k_lo * HW_;

    int sidx[3], sh[3], sw[3];
    bool sval[3];
#pragma unroll
    for (int i = 0; i < 3; i++) {
        int idx = tid + i * 256;
        sidx[i] = idx;
        int r = idx / 34, cc = idx - r * 34;
        sh[i] = h0 - 1 + r;
        sw[i] = w0 - 1 + cc;
        sval[i] = (idx < 612) && (sh[i] >= 0) && (sh[i] < H_) && (sw[i] >= 0) && (sw[i] < W_);
    }

#pragma unroll
    for (int i = 0; i < 3; i++) {
        if (sidx[i] < 612) {
            float v = sval[i] ? xb[sh[i] * W_ + sw[i]] : 0.f;
            xt2[0][sidx[i]] = v;
        }
    }
    __syncthreads();

    float2 acc0[4], acc1[4];
#pragma unroll
    for (int q = 0; q < 4; q++) { acc0[q] = make_float2(0.f, 0.f); acc1[q] = make_float2(0.f, 0.f); }

    for (int k = 0; k < 32; k++) {
        int cur = k & 1;

        float pf[3] = {0.f, 0.f, 0.f};
        if (k + 1 < 32) {
            const float* xk = xb + (size_t)(k + 1) * HW_;
#pragma unroll
            for (int i = 0; i < 3; i++)
                if (sval[i]) pf[i] = xk[sh[i] * W_ + sw[i]];
        }

        const float* xtc = &xt2[cur][0];
        float xv[3][4];
#pragma unroll
        for (int r = 0; r < 3; r++)
#pragma unroll
            for (int c = 0; c < 4; c++) xv[r][c] = xtc[(ty + r) * 34 + 2 * tx + c];

        const float* wk = &ws[k * 72];
#pragma unroll
        for (int t = 0; t < 9; t++) {
            int dy = t / 3, dx = t - dy * 3;
            float2 wp[4];
            *(float4*)&wp[0] = *(const float4*)&wk[t * 8 + 0];
            *(float4*)&wp[2] = *(const float4*)&wk[t * 8 + 4];
            float2 xp0 = make_float2(xv[dy][dx], xv[dy][dx]);
            float2 xp1 = make_float2(xv[dy][dx + 1], xv[dy][dx + 1]);
#pragma unroll
            for (int q = 0; q < 4; q++) {
                acc0[q] = fma2(xp0, wp[q], acc0[q]);
                acc1[q] = fma2(xp1, wp[q], acc1[q]);
            }
        }

        if (k + 1 < 32) {
            int nb = cur ^ 1;
#pragma unroll
            for (int i = 0; i < 3; i++)
                if (sidx[i] < 612) xt2[nb][sidx[i]] = pf[i];
        }
        __syncthreads();
    }

    int y = h0 + ty;
    int xw = w0 + 2 * tx;
    float* pbase = d_part + (size_t)(split * B_ + b) * 8 * HW_;
#pragma unroll
    for (int q = 0; q < 4; q++) {
        float a0[2] = { acc0[q].x, acc0[q].y };
        float a1[2] = { acc1[q].x, acc1[q].y };
#pragma unroll
        for (int h = 0; h < 2; h++) {
            int oc = q * 2 + h;
            size_t base = (size_t)oc * HW_ + y * W_ + xw;
            pbase[base] = a0[h];
            pbase[base + 1] = a1[h];
        }
    }
}

// ---------------------------------------------------------------------------
// K2b: reduce 4 partials + bias + tanh -> d_off. Vectorized float4.
// ---------------------------------------------------------------------------
__global__ void k2b_reduce(const float* __restrict__ b_off) {
    int i = blockIdx.x * blockDim.x + threadIdx.x;   // over N/4 float4s
    const int N4 = B_ * 8 * HW_ / 4;
    if (i >= N4) return;
    int e = i * 4;
    int r = e & (8 * HW_ - 1);          // within-batch element
    int b = e / (8 * HW_);
    int oc = r / HW_;

    const float4* p0 = (const float4*)(d_part + ((size_t)(0 * B_ + b) * 8) * HW_ + r);
    const float4* p1 = (const float4*)(d_part + ((size_t)(1 * B_ + b) * 8) * HW_ + r);
    const float4* p2 = (const float4*)(d_part + ((size_t)(2 * B_ + b) * 8) * HW_ + r);
    const float4* p3 = (const float4*)(d_part + ((size_t)(3 * B_ + b) * 8) * HW_ + r);
    float4 v0 = *p0, v1 = *p1, v2 = *p2, v3 = *p3;
    float bo = b_off[oc];
    float4 o;
    o.x = tanhf(v0.x + v1.x + v2.x + v3.x + bo);
    o.y = tanhf(v0.y + v1.y + v2.y + v3.y + bo);
    o.z = tanhf(v0.z + v1.z + v2.z + v3.z + bo);
    o.w = tanhf(v0.w + v1.w + v2.w + v3.w + bo);
    *(float4*)(d_off + e) = o;
}

// ---------------------------------------------------------------------------
// K3: offset upsample + grid_sample + transposed store, with SMEM p-tile.
//     Offsets are bounded (|tanh|<1, scale 63/128 < 0.5px), so a 4x32 output
//     block samples only a <=5x18 input window x 32ch -> stage it in smem.
// ---------------------------------------------------------------------------
#define TW_ 18
#define TH_ 5
__global__ __launch_bounds__(1024) void k3_sample(float* __restrict__ out) {
    int bx = blockIdx.x;
    int ys0 = (bx >> 2) * 4;
    int xs0 = (bx & 3) * 32;
    int g = blockIdx.y;
    int b = blockIdx.z;
    int tid = threadIdx.x;
    int warp = tid >> 5;
    int lane = tid & 31;

    __shared__ float tile[TH_ * TW_ * CG_];   // 11.25KB input window
    __shared__ int   s_r[4][32][4];           // tile-relative corner offs (*CG_)
    __shared__ float s_f[4][32][2];           // fx, fy
    __shared__ float tr[4][32][33];           // transpose buffers

    const float SY = 63.0f / 127.0f;
    const float SO = 63.0f / 128.0f;

    int x_lo = max(0, (int)floorf(xs0 * SY - 0.4923f));
    int y_lo = max(0, (int)floorf(ys0 * SY - 0.4923f));

    // ---- cooperative tile load (all 1024 threads) ----
    const float* pb = d_p + (size_t)(b * G_ + g) * HW_ * CG_;
    for (int idx = tid; idx < TH_ * TW_ * CG_; idx += 1024) {
        int ry = idx / (TW_ * CG_);
        int rem = idx - ry * (TW_ * CG_);
        int rx = rem >> 5;
        int c = rem & 31;
        int y = min(y_lo + ry, H_ - 1);
        int x = min(x_lo + rx, W_ - 1);
        tile[idx] = pb[(y * W_ + x) * CG_ + c];
    }

    // ---- Phase A: 128 threads compute per-pixel coords ----
    if (tid < 128) {
        int r = tid >> 5;
        int xl = tid & 31;
        int ys = ys0 + r;
        int xs = xs0 + xl;

        float py = ys * SY;
        int y0u = (int)py;
        float wyu = py - y0u;
        int y1u = min(y0u + 1, H_ - 1);
        float px = xs * SY;
        int x0u = (int)px;
        float wxu = px - x0u;
        int x1u = min(x0u + 1, W_ - 1);

        const float* offx = d_off + (size_t)(b * 8 + 2 * g) * HW_;
        const float* offy = offx + HW_;

        float a00 = offx[y0u * W_ + x0u], a01 = offx[y0u * W_ + x1u];
        float a10 = offx[y1u * W_ + x0u], a11 = offx[y1u * W_ + x1u];
        float o_x = (a00 * (1.f - wxu) + a01 * wxu) * (1.f - wyu)
                  + (a10 * (1.f - wxu) + a11 * wxu) * wyu;

        float c00 = offy[y0u * W_ + x0u], c01 = offy[y0u * W_ + x1u];
        float c10 = offy[y1u * W_ + x0u], c11 = offy[y1u * W_ + x1u];
        float o_y = (c00 * (1.f - wxu) + c01 * wxu) * (1.f - wyu)
                  + (c10 * (1.f - wxu) + c11 * wxu) * wyu;

        float ix = fminf(fmaxf(px + o_x * SO, 0.f), (float)(W_ - 1));
        float iy = fminf(fmaxf(py + o_y * SO, 0.f), (float)(H_ - 1));

        int ix0 = (int)ix; if (ix0 > W_ - 1) ix0 = W_ - 1;
        int iy0 = (int)iy; if (iy0 > H_ - 1) iy0 = H_ - 1;
        int ix1 = min(ix0 + 1, W_ - 1);
        int iy1 = min(iy0 + 1, H_ - 1);

        int base = ((iy0 - y_lo) * TW_ + (ix0 - x_lo)) * CG_;
        int dxo = (ix1 - ix0) * CG_;
        int dyo = (iy1 - iy0) * TW_ * CG_;
        s_r[r][xl][0] = base;
        s_r[r][xl][1] = base + dxo;
        s_r[r][xl][2] = base + dyo;
        s_r[r][xl][3] = base + dyo + dxo;
        s_f[r][xl][0] = ix - ix0;
        s_f[r][xl][1] = iy - iy0;
    }
    __syncthreads();

    // ---- Phase B: half-warp = pixel, lane handles 2 channels, from smem ----
    const float2* tile2 = (const float2*)tile;
    int half = lane >> 4;
    int l16 = lane & 15;
#pragma unroll
    for (int it = 0; it < 2; it++) {
        int pix = warp * 2 + half + it * 64;
        int r = pix >> 5, cc = pix & 31;

        int r00 = s_r[r][cc][0] >> 1;
        int r01 = s_r[r][cc][1] >> 1;
        int r10 = s_r[r][cc][2] >> 1;
        int r11 = s_r[r][cc][3] >> 1;
        float fx = s_f[r][cc][0];
        float fy = s_f[r][cc][1];

        float2 v00 = tile2[r00 + l16];
        float2 v01 = tile2[r01 + l16];
        float2 v10 = tile2[r10 + l16];
        float2 v11 = tile2[r11 + l16];

        float2 fx2  = make_float2(fx, fx);
        float2 ofx2 = make_float2(1.f - fx, 1.f - fx);
        float2 fy2  = make_float2(fy, fy);
        float2 ofy2 = make_float2(1.f - fy, 1.f - fy);

        float2 t0 = fma2(v00, ofx2, mul2(v01, fx2));
        float2 t1 = fma2(v10, ofx2, mul2(v11, fx2));
        float2 res = fma2(t0, ofy2, mul2(t1, fy2));

        tr[r][cc][2 * l16]     = res.x;
        tr[r][cc][2 * l16 + 1] = res.y;
    }
    __syncthreads();

    // ---- coalesced store: warp w owns channel w, writes 4 rows of 32 px ----
    size_t obase = ((size_t)(b * C_ + g * CG_ + warp)) * HS_ * WS_;
#pragma unroll
    for (int r = 0; r < 4; r++) {
        out[obase + (size_t)(ys0 + r) * WS_ + xs0 + lane] = tr[r][lane][warp];
    }
}

// ---------------------------------------------------------------------------
extern "C" void kernel_launch(void* const* d_in, const int* in_sizes, int n_in,
                              void* d_out, int out_size) {
    const float* x      = (const float*)d_in[0];
    const float* w_off  = (const float*)d_in[1];
    const float* b_off  = (const float*)d_in[2];
    const float* w_proj = (const float*)d_in[3];
    const float* gamma  = (const float*)d_in[4];
    const float* beta   = (const float*)d_in[5];
    const float* mean   = (const float*)d_in[6];
    const float* var    = (const float*)d_in[7];
    float* out = (float*)d_out;

    k0_prep<<<16, 1024>>>(w_proj, gamma, beta, mean, var);

    dim3 g2(W_ / 32, H_ / 16, B_ * 4);
    k2a_conv3<<<g2, dim3(16, 16)>>>(x, w_off);

    dim3 g1(HW_ / 128, B_);
    k1_gemm<<<g1, 256>>>(x);

    int n4 = B_ * 8 * HW_ / 4;
    k2b_reduce<<<(n4 + 255) / 256, 256>>>(b_off);

    dim3 g3((HS_ / 4) * (WS_ / 32), G_, B_);
    k3_sample<<<g3, 1024>>>(out);
}

// round 7
// speedup vs baseline: 2.3114x; 1.1507x over previous
#include <cuda_runtime.h>
#include <math.h>
#include <stdint.h>

// Problem constants (fixed shapes)
#define B_  16
#define C_  128
#define H_  64
#define W_  64
#define G_  4
#define CG_ 32
#define HW_ 4096      // H_*W_
#define HS_ 128
#define WS_ 128

// Scratch (static device globals; no runtime allocation)
__device__ uint32_t d_Wt[C_ * C_];         // Wt[k][n] = tf32(w_proj[n,k] * bn_scale[n])
__device__ float d_tb[C_];                 // folded bias
__device__ float d_p[B_ * G_ * HW_ * CG_]; // p in (b,g,pix,cg) layout, 33.5MB
__device__ float d_off[B_ * 8 * HW_];      // tanh offsets, NCHW (B,2G,H,W)
__device__ float d_part[4 * B_ * 8 * HW_]; // K2 k-split partial sums, 8MB

// ---- packed fp32x2 helpers ----
__device__ __forceinline__ float2 fma2(float2 a, float2 b, float2 c) {
    float2 d;
    asm("fma.rn.f32x2 %0, %1, %2, %3;"
        : "=l"(reinterpret_cast<unsigned long long&>(d))
        : "l"(reinterpret_cast<unsigned long long&>(a)),
          "l"(reinterpret_cast<unsigned long long&>(b)),
          "l"(reinterpret_cast<unsigned long long&>(c)));
    return d;
}
__device__ __forceinline__ float2 mul2(float2 a, float2 b) {
    float2 d;
    asm("mul.rn.f32x2 %0, %1, %2;"
        : "=l"(reinterpret_cast<unsigned long long&>(d))
        : "l"(reinterpret_cast<unsigned long long&>(a)),
          "l"(reinterpret_cast<unsigned long long&>(b)));
    return d;
}
__device__ __forceinline__ uint32_t to_tf32(float v) {
    uint32_t u;
    asm("cvt.rna.tf32.f32 %0, %1;" : "=r"(u) : "f"(v));
    return u;
}

// ---------------------------------------------------------------------------
// K0: fold BN into transposed weights (tf32-rounded) + folded bias
// ---------------------------------------------------------------------------
__global__ void k0_prep(const float* __restrict__ w_proj,
                        const float* __restrict__ gamma,
                        const float* __restrict__ beta,
                        const float* __restrict__ mean,
                        const float* __restrict__ var) {
    int idx = blockIdx.x * blockDim.x + threadIdx.x;
    if (idx >= C_ * C_) return;
    int k = idx >> 7;        // in-channel (GEMM K)
    int n = idx & 127;       // out-channel (GEMM N)
    float s = gamma[n] * rsqrtf(var[n] + 1e-5f);
    d_Wt[k * C_ + n] = to_tf32(w_proj[n * C_ + k] * s);
    if (idx < C_) {
        d_tb[idx] = beta[idx] - mean[idx] * (gamma[idx] * rsqrtf(var[idx] + 1e-5f));
    }
}

// ---------------------------------------------------------------------------
// K1: 1x1 conv as TF32 mma.sync GEMM. Block tile: 128 px x 128 ch; K chunked
//     into 4 panels of 32. 8 warps, warp tile 32x64 (2x8 m16n8k8 frags).
//     Smem row stride 136 floats -> fragment LDS hits bank 8*tg+gid (no conflicts).
// ---------------------------------------------------------------------------
#define SKSTR 136
__global__ __launch_bounds__(256) void k1_mma(const float* __restrict__ x) {
    __shared__ uint32_t As[32 * SKSTR];    // [k][m], tf32 bits (17.4KB)
    __shared__ uint32_t Bs[32 * SKSTR];    // [k][n], tf32 bits
    __shared__ float sTb[128];

    int b = blockIdx.y;
    int pix0 = blockIdx.x * 128;
    int t = threadIdx.x;
    int wid = t >> 5;
    int lane = t & 31;
    int gid = lane >> 2;     // 0..7
    int tg = lane & 3;       // 0..3
    int mbase = (wid & 3) * 32;
    int nbase = (wid >> 2) * 64;

    if (t < 128) sTb[t] = d_tb[t];

    const float* xb = x + (size_t)b * C_ * HW_ + pix0;

    float acc[2][8][4];
#pragma unroll
    for (int mt = 0; mt < 2; mt++)
#pragma unroll
        for (int nt = 0; nt < 8; nt++)
#pragma unroll
            for (int q = 0; q < 4; q++) acc[mt][nt][q] = 0.f;

    // thread's fill slots: i in {t, t+256, t+512, t+768}; k = i>>5, c = (i&31)*4
    for (int k0 = 0; k0 < 128; k0 += 32) {
        __syncthreads();
#pragma unroll
        for (int i = t; i < 1024; i += 256) {
            int k = i >> 5;
            int c = (i & 31) * 4;
            float4 v = *(const float4*)&xb[(size_t)(k0 + k) * HW_ + c];
            uint32_t* dst = &As[k * SKSTR + c];
            dst[0] = to_tf32(v.x); dst[1] = to_tf32(v.y);
            dst[2] = to_tf32(v.z); dst[3] = to_tf32(v.w);
            *(uint4*)&Bs[k * SKSTR + c] = *(const uint4*)&d_Wt[(k0 + k) * C_ + c];
        }
        __syncthreads();

#pragma unroll
        for (int ks = 0; ks < 4; ks++) {
            int kk = ks * 8;
            uint32_t a[2][4];
#pragma unroll
            for (int mt = 0; mt < 2; mt++) {
                int m = mbase + mt * 16 + gid;
                a[mt][0] = As[(kk + tg) * SKSTR + m];
                a[mt][1] = As[(kk + tg) * SKSTR + m + 8];
                a[mt][2] = As[(kk + tg + 4) * SKSTR + m];
                a[mt][3] = As[(kk + tg + 4) * SKSTR + m + 8];
            }
#pragma unroll
            for (int nt = 0; nt < 8; nt++) {
                int n = nbase + nt * 8 + gid;
                uint32_t b0 = Bs[(kk + tg) * SKSTR + n];
                uint32_t b1 = Bs[(kk + tg + 4) * SKSTR + n];
#pragma unroll
                for (int mt = 0; mt < 2; mt++) {
                    asm volatile(
                        "mma.sync.aligned.m16n8k8.row.col.f32.tf32.tf32.f32 "
                        "{%0,%1,%2,%3}, {%4,%5,%6,%7}, {%8,%9}, {%0,%1,%2,%3};"
                        : "+f"(acc[mt][nt][0]), "+f"(acc[mt][nt][1]),
                          "+f"(acc[mt][nt][2]), "+f"(acc[mt][nt][3])
                        : "r"(a[mt][0]), "r"(a[mt][1]), "r"(a[mt][2]), "r"(a[mt][3]),
                          "r"(b0), "r"(b1));
                }
            }
        }
    }

    // Epilogue: bias + SiLU, float2 stores to group-NHWC d_p
#pragma unroll
    for (int mt = 0; mt < 2; mt++) {
        int pixA = pix0 + mbase + mt * 16 + gid;
        int pixB = pixA + 8;
#pragma unroll
        for (int nt = 0; nt < 8; nt++) {
            int n = nbase + nt * 8 + 2 * tg;
            int g = n >> 5, cg = n & 31;
            float t0 = sTb[n], t1 = sTb[n + 1];
            float u;
            float2 vA, vB;
            u = acc[mt][nt][0] + t0; vA.x = u * (1.f / (1.f + __expf(-u)));
            u = acc[mt][nt][1] + t1; vA.y = u * (1.f / (1.f + __expf(-u)));
            u = acc[mt][nt][2] + t0; vB.x = u * (1.f / (1.f + __expf(-u)));
            u = acc[mt][nt][3] + t1; vB.y = u * (1.f / (1.f + __expf(-u)));
            float* base = d_p + ((size_t)(b * G_ + g) * HW_) * CG_ + cg;
            *(float2*)(base + (size_t)pixA * CG_) = vA;
            *(float2*)(base + (size_t)pixB * CG_) = vB;
        }
    }
}

// ---------------------------------------------------------------------------
// K2a: 3x3 conv partials over a 32-channel k-slice (4-way k-split)
// ---------------------------------------------------------------------------
__global__ __launch_bounds__(256, 4) void k2a_conv3(const float* __restrict__ x,
                                                    const float* __restrict__ w_off) {
    __shared__ float ws[32 * 9 * 8];
    __shared__ float xt2[2][18 * 34];

    int bz = blockIdx.z;
    int b = bz >> 2;
    int split = bz & 3;
    int k_lo = split * 32;
    int h0 = blockIdx.y * 16;
    int w0 = blockIdx.x * 32;
    int tid = threadIdx.y * 16 + threadIdx.x;
    int tx = threadIdx.x;
    int ty = threadIdx.y;

    for (int idx = tid; idx < 32 * 9 * 8; idx += 256) {
        int kk = idx / 72;
        int r = idx - kk * 72;
        int t = r >> 3;
        int oc = r & 7;
        ws[idx] = w_off[oc * (C_ * 9) + (k_lo + kk) * 9 + t];
    }

    const float* xb = x + (size_t)b * C_ * HW_ + (size_t)k_lo * HW_;

    int sidx[3], sh[3], sw[3];
    bool sval[3];
#pragma unroll
    for (int i = 0; i < 3; i++) {
        int idx = tid + i * 256;
        sidx[i] = idx;
        int r = idx / 34, cc = idx - r * 34;
        sh[i] = h0 - 1 + r;
        sw[i] = w0 - 1 + cc;
        sval[i] = (idx < 612) && (sh[i] >= 0) && (sh[i] < H_) && (sw[i] >= 0) && (sw[i] < W_);
    }

#pragma unroll
    for (int i = 0; i < 3; i++) {
        if (sidx[i] < 612) {
            float v = sval[i] ? xb[sh[i] * W_ + sw[i]] : 0.f;
            xt2[0][sidx[i]] = v;
        }
    }
    __syncthreads();

    float2 acc0[4], acc1[4];
#pragma unroll
    for (int q = 0; q < 4; q++) { acc0[q] = make_float2(0.f, 0.f); acc1[q] = make_float2(0.f, 0.f); }

    for (int k = 0; k < 32; k++) {
        int cur = k & 1;

        float pf[3] = {0.f, 0.f, 0.f};
        if (k + 1 < 32) {
            const float* xk = xb + (size_t)(k + 1) * HW_;
#pragma unroll
            for (int i = 0; i < 3; i++)
                if (sval[i]) pf[i] = xk[sh[i] * W_ + sw[i]];
        }

        const float* xtc = &xt2[cur][0];
        float xv[3][4];
#pragma unroll
        for (int r = 0; r < 3; r++)
#pragma unroll
            for (int c = 0; c < 4; c++) xv[r][c] = xtc[(ty + r) * 34 + 2 * tx + c];

        const float* wk = &ws[k * 72];
#pragma unroll
        for (int t = 0; t < 9; t++) {
            int dy = t / 3, dx = t - dy * 3;
            float2 wp[4];
            *(float4*)&wp[0] = *(const float4*)&wk[t * 8 + 0];
            *(float4*)&wp[2] = *(const float4*)&wk[t * 8 + 4];
            float2 xp0 = make_float2(xv[dy][dx], xv[dy][dx]);
            float2 xp1 = make_float2(xv[dy][dx + 1], xv[dy][dx + 1]);
#pragma unroll
            for (int q = 0; q < 4; q++) {
                acc0[q] = fma2(xp0, wp[q], acc0[q]);
                acc1[q] = fma2(xp1, wp[q], acc1[q]);
            }
        }

        if (k + 1 < 32) {
            int nb = cur ^ 1;
#pragma unroll
            for (int i = 0; i < 3; i++)
                if (sidx[i] < 612) xt2[nb][sidx[i]] = pf[i];
        }
        __syncthreads();
    }

    int y = h0 + ty;
    int xw = w0 + 2 * tx;
    float* pbase = d_part + (size_t)(split * B_ + b) * 8 * HW_;
#pragma unroll
    for (int q = 0; q < 4; q++) {
        float a0[2] = { acc0[q].x, acc0[q].y };
        float a1[2] = { acc1[q].x, acc1[q].y };
#pragma unroll
        for (int h = 0; h < 2; h++) {
            int oc = q * 2 + h;
            size_t base = (size_t)oc * HW_ + y * W_ + xw;
            pbase[base] = a0[h];
            pbase[base + 1] = a1[h];
        }
    }
}

// ---------------------------------------------------------------------------
// K2b: reduce 4 partials + bias + tanh -> d_off
// ---------------------------------------------------------------------------
__global__ void k2b_reduce(const float* __restrict__ b_off) {
    int i = blockIdx.x * blockDim.x + threadIdx.x;
    const int N4 = B_ * 8 * HW_ / 4;
    if (i >= N4) return;
    int e = i * 4;
    int r = e & (8 * HW_ - 1);
    int b = e / (8 * HW_);
    int oc = r / HW_;

    const float4* p0 = (const float4*)(d_part + ((size_t)(0 * B_ + b) * 8) * HW_ + r);
    const float4* p1 = (const float4*)(d_part + ((size_t)(1 * B_ + b) * 8) * HW_ + r);
    const float4* p2 = (const float4*)(d_part + ((size_t)(2 * B_ + b) * 8) * HW_ + r);
    const float4* p3 = (const float4*)(d_part + ((size_t)(3 * B_ + b) * 8) * HW_ + r);
    float4 v0 = *p0, v1 = *p1, v2 = *p2, v3 = *p3;
    float bo = b_off[oc];
    float4 o;
    o.x = tanhf(v0.x + v1.x + v2.x + v3.x + bo);
    o.y = tanhf(v0.y + v1.y + v2.y + v3.y + bo);
    o.z = tanhf(v0.z + v1.z + v2.z + v3.z + bo);
    o.w = tanhf(v0.w + v1.w + v2.w + v3.w + bo);
    *(float4*)(d_off + e) = o;
}

// ---------------------------------------------------------------------------
// K3: offset upsample + grid_sample + transposed store, with SMEM p-tile.
// ---------------------------------------------------------------------------
#define TW_ 18
#define TH_ 5
__global__ __launch_bounds__(1024) void k3_sample(float* __restrict__ out) {
    int bx = blockIdx.x;
    int ys0 = (bx >> 2) * 4;
    int xs0 = (bx & 3) * 32;
    int g = blockIdx.y;
    int b = blockIdx.z;
    int tid = threadIdx.x;
    int warp = tid >> 5;
    int lane = tid & 31;

    __shared__ float tile[TH_ * TW_ * CG_];
    __shared__ int   s_r[4][32][4];
    __shared__ float s_f[4][32][2];
    __shared__ float tr[4][32][33];

    const float SY = 63.0f / 127.0f;
    const float SO = 63.0f / 128.0f;

    int x_lo = max(0, (int)floorf(xs0 * SY - 0.4923f));
    int y_lo = max(0, (int)floorf(ys0 * SY - 0.4923f));

    const float* pb = d_p + (size_t)(b * G_ + g) * HW_ * CG_;
    for (int idx = tid; idx < TH_ * TW_ * CG_; idx += 1024) {
        int ry = idx / (TW_ * CG_);
        int rem = idx - ry * (TW_ * CG_);
        int rx = rem >> 5;
        int c = rem & 31;
        int y = min(y_lo + ry, H_ - 1);
        int x = min(x_lo + rx, W_ - 1);
        tile[idx] = pb[(y * W_ + x) * CG_ + c];
    }

    if (tid < 128) {
        int r = tid >> 5;
        int xl = tid & 31;
        int ys = ys0 + r;
        int xs = xs0 + xl;

        float py = ys * SY;
        int y0u = (int)py;
        float wyu = py - y0u;
        int y1u = min(y0u + 1, H_ - 1);
        float px = xs * SY;
        int x0u = (int)px;
        float wxu = px - x0u;
        int x1u = min(x0u + 1, W_ - 1);

        const float* offx = d_off + (size_t)(b * 8 + 2 * g) * HW_;
        const float* offy = offx + HW_;

        float a00 = offx[y0u * W_ + x0u], a01 = offx[y0u * W_ + x1u];
        float a10 = offx[y1u * W_ + x0u], a11 = offx[y1u * W_ + x1u];
        float o_x = (a00 * (1.f - wxu) + a01 * wxu) * (1.f - wyu)
                  + (a10 * (1.f - wxu) + a11 * wxu) * wyu;

        float c00 = offy[y0u * W_ + x0u], c01 = offy[y0u * W_ + x1u];
        float c10 = offy[y1u * W_ + x0u], c11 = offy[y1u * W_ + x1u];
        float o_y = (c00 * (1.f - wxu) + c01 * wxu) * (1.f - wyu)
                  + (c10 * (1.f - wxu) + c11 * wxu) * wyu;

        float ix = fminf(fmaxf(px + o_x * SO, 0.f), (float)(W_ - 1));
        float iy = fminf(fmaxf(py + o_y * SO, 0.f), (float)(H_ - 1));

        int ix0 = (int)ix; if (ix0 > W_ - 1) ix0 = W_ - 1;
        int iy0 = (int)iy; if (iy0 > H_ - 1) iy0 = H_ - 1;
        int ix1 = min(ix0 + 1, W_ - 1);
        int iy1 = min(iy0 + 1, H_ - 1);

        int base = ((iy0 - y_lo) * TW_ + (ix0 - x_lo)) * CG_;
        int dxo = (ix1 - ix0) * CG_;
        int dyo = (iy1 - iy0) * TW_ * CG_;
        s_r[r][xl][0] = base;
        s_r[r][xl][1] = base + dxo;
        s_r[r][xl][2] = base + dyo;
        s_r[r][xl][3] = base + dyo + dxo;
        s_f[r][xl][0] = ix - ix0;
        s_f[r][xl][1] = iy - iy0;
    }
    __syncthreads();

    const float2* tile2 = (const float2*)tile;
    int half = lane >> 4;
    int l16 = lane & 15;
#pragma unroll
    for (int it = 0; it < 2; it++) {
        int pix = warp * 2 + half + it * 64;
        int r = pix >> 5, cc = pix & 31;

        int r00 = s_r[r][cc][0] >> 1;
        int r01 = s_r[r][cc][1] >> 1;
        int r10 = s_r[r][cc][2] >> 1;
        int r11 = s_r[r][cc][3] >> 1;
        float fx = s_f[r][cc][0];
        float fy = s_f[r][cc][1];

        float2 v00 = tile2[r00 + l16];
        float2 v01 = tile2[r01 + l16];
        float2 v10 = tile2[r10 + l16];
        float2 v11 = tile2[r11 + l16];

        float2 fx2  = make_float2(fx, fx);
        float2 ofx2 = make_float2(1.f - fx, 1.f - fx);
        float2 fy2  = make_float2(fy, fy);
        float2 ofy2 = make_float2(1.f - fy, 1.f - fy);

        float2 t0 = fma2(v00, ofx2, mul2(v01, fx2));
        float2 t1 = fma2(v10, ofx2, mul2(v11, fx2));
        float2 res = fma2(t0, ofy2, mul2(t1, fy2));

        tr[r][cc][2 * l16]     = res.x;
        tr[r][cc][2 * l16 + 1] = res.y;
    }
    __syncthreads();

    size_t obase = ((size_t)(b * C_ + g * CG_ + warp)) * HS_ * WS_;
#pragma unroll
    for (int r = 0; r < 4; r++) {
        out[obase + (size_t)(ys0 + r) * WS_ + xs0 + lane] = tr[r][lane][warp];
    }
}

// ---------------------------------------------------------------------------
extern "C" void kernel_launch(void* const* d_in, const int* in_sizes, int n_in,
                              void* d_out, int out_size) {
    const float* x      = (const float*)d_in[0];
    const float* w_off  = (const float*)d_in[1];
    const float* b_off  = (const float*)d_in[2];
    const float* w_proj = (const float*)d_in[3];
    const float* gamma  = (const float*)d_in[4];
    const float* beta   = (const float*)d_in[5];
    const float* mean   = (const float*)d_in[6];
    const float* var    = (const float*)d_in[7];
    float* out = (float*)d_out;

    k0_prep<<<16, 1024>>>(w_proj, gamma, beta, mean, var);

    dim3 g2(W_ / 32, H_ / 16, B_ * 4);
    k2a_conv3<<<g2, dim3(16, 16)>>>(x, w_off);

    dim3 g1(HW_ / 128, B_);
    k1_mma<<<g1, 256>>>(x);

    int n4 = B_ * 8 * HW_ / 4;
    k2b_reduce<<<(n4 + 255) / 256, 256>>>(b_off);

    dim3 g3((HS_ / 4) * (WS_ / 32), G_, B_);
    k3_sample<<<g3, 1024>>>(out);
}

// round 8
// speedup vs baseline: 2.9178x; 1.2623x over previous
#include <cuda_runtime.h>
#include <math.h>
#include <stdint.h>

// Problem constants (fixed shapes)
#define B_  16
#define C_  128
#define H_  64
#define W_  64
#define G_  4
#define CG_ 32
#define HW_ 4096      // H_*W_
#define HS_ 128
#define WS_ 128

// Scratch (static device globals; no runtime allocation)
__device__ uint32_t d_Wt[C_ * C_];         // Wt[k][n] = tf32(w_proj[n,k] * bn_scale[n])
__device__ float d_tb[C_];                 // folded bias
__device__ float d_p[B_ * G_ * HW_ * CG_]; // p in (b,g,pix,cg) layout, 33.5MB
__device__ float d_off[B_ * 8 * HW_];      // tanh offsets, NCHW (B,2G,H,W)
__device__ float d_part[4 * B_ * 8 * HW_]; // K2 k-split partial sums, 8MB

// ---- packed fp32x2 helpers ----
__device__ __forceinline__ float2 fma2(float2 a, float2 b, float2 c) {
    float2 d;
    asm("fma.rn.f32x2 %0, %1, %2, %3;"
        : "=l"(reinterpret_cast<unsigned long long&>(d))
        : "l"(reinterpret_cast<unsigned long long&>(a)),
          "l"(reinterpret_cast<unsigned long long&>(b)),
          "l"(reinterpret_cast<unsigned long long&>(c)));
    return d;
}
__device__ __forceinline__ uint32_t to_tf32(float v) {
    uint32_t u;
    asm("cvt.rna.tf32.f32 %0, %1;" : "=r"(u) : "f"(v));
    return u;
}

// ---------------------------------------------------------------------------
// K0: fold BN into transposed weights (tf32-rounded) + folded bias
// ---------------------------------------------------------------------------
__global__ void k0_prep(const float* __restrict__ w_proj,
                        const float* __restrict__ gamma,
                        const float* __restrict__ beta,
                        const float* __restrict__ mean,
                        const float* __restrict__ var) {
    int idx = blockIdx.x * blockDim.x + threadIdx.x;
    if (idx >= C_ * C_) return;
    int k = idx >> 7;        // in-channel (GEMM K)
    int n = idx & 127;       // out-channel (GEMM N)
    float s = gamma[n] * rsqrtf(var[n] + 1e-5f);
    d_Wt[k * C_ + n] = to_tf32(w_proj[n * C_ + k] * s);
    if (idx < C_) {
        d_tb[idx] = beta[idx] - mean[idx] * (gamma[idx] * rsqrtf(var[idx] + 1e-5f));
    }
}

// ---------------------------------------------------------------------------
// K1: 1x1 conv as TF32 mma.sync GEMM. Block tile: 128 px x 128 ch; K chunked
//     into 4 panels of 32. 8 warps, warp tile 32x64 (2x8 m16n8k8 frags).
// ---------------------------------------------------------------------------
#define SKSTR 136
__global__ __launch_bounds__(256) void k1_mma(const float* __restrict__ x) {
    __shared__ uint32_t As[32 * SKSTR];    // [k][m], tf32 bits
    __shared__ uint32_t Bs[32 * SKSTR];    // [k][n], tf32 bits
    __shared__ float sTb[128];

    int b = blockIdx.y;
    int pix0 = blockIdx.x * 128;
    int t = threadIdx.x;
    int wid = t >> 5;
    int lane = t & 31;
    int gid = lane >> 2;     // 0..7
    int tg = lane & 3;       // 0..3
    int mbase = (wid & 3) * 32;
    int nbase = (wid >> 2) * 64;

    if (t < 128) sTb[t] = d_tb[t];

    const float* xb = x + (size_t)b * C_ * HW_ + pix0;

    float acc[2][8][4];
#pragma unroll
    for (int mt = 0; mt < 2; mt++)
#pragma unroll
        for (int nt = 0; nt < 8; nt++)
#pragma unroll
            for (int q = 0; q < 4; q++) acc[mt][nt][q] = 0.f;

    for (int k0 = 0; k0 < 128; k0 += 32) {
        __syncthreads();
#pragma unroll
        for (int i = t; i < 1024; i += 256) {
            int k = i >> 5;
            int c = (i & 31) * 4;
            float4 v = *(const float4*)&xb[(size_t)(k0 + k) * HW_ + c];
            uint32_t* dst = &As[k * SKSTR + c];
            dst[0] = to_tf32(v.x); dst[1] = to_tf32(v.y);
            dst[2] = to_tf32(v.z); dst[3] = to_tf32(v.w);
            *(uint4*)&Bs[k * SKSTR + c] = *(const uint4*)&d_Wt[(k0 + k) * C_ + c];
        }
        __syncthreads();

#pragma unroll
        for (int ks = 0; ks < 4; ks++) {
            int kk = ks * 8;
            uint32_t a[2][4];
#pragma unroll
            for (int mt = 0; mt < 2; mt++) {
                int m = mbase + mt * 16 + gid;
                a[mt][0] = As[(kk + tg) * SKSTR + m];
                a[mt][1] = As[(kk + tg) * SKSTR + m + 8];
                a[mt][2] = As[(kk + tg + 4) * SKSTR + m];
                a[mt][3] = As[(kk + tg + 4) * SKSTR + m + 8];
            }
#pragma unroll
            for (int nt = 0; nt < 8; nt++) {
                int n = nbase + nt * 8 + gid;
                uint32_t b0 = Bs[(kk + tg) * SKSTR + n];
                uint32_t b1 = Bs[(kk + tg + 4) * SKSTR + n];
#pragma unroll
                for (int mt = 0; mt < 2; mt++) {
                    asm volatile(
                        "mma.sync.aligned.m16n8k8.row.col.f32.tf32.tf32.f32 "
                        "{%0,%1,%2,%3}, {%4,%5,%6,%7}, {%8,%9}, {%0,%1,%2,%3};"
                        : "+f"(acc[mt][nt][0]), "+f"(acc[mt][nt][1]),
                          "+f"(acc[mt][nt][2]), "+f"(acc[mt][nt][3])
                        : "r"(a[mt][0]), "r"(a[mt][1]), "r"(a[mt][2]), "r"(a[mt][3]),
                          "r"(b0), "r"(b1));
                }
            }
        }
    }

    // Epilogue: bias + SiLU, float2 stores to group-NHWC d_p
#pragma unroll
    for (int mt = 0; mt < 2; mt++) {
        int pixA = pix0 + mbase + mt * 16 + gid;
        int pixB = pixA + 8;
#pragma unroll
        for (int nt = 0; nt < 8; nt++) {
            int n = nbase + nt * 8 + 2 * tg;
            int g = n >> 5, cg = n & 31;
            float t0 = sTb[n], t1 = sTb[n + 1];
            float u;
            float2 vA, vB;
            u = acc[mt][nt][0] + t0; vA.x = u * (1.f / (1.f + __expf(-u)));
            u = acc[mt][nt][1] + t1; vA.y = u * (1.f / (1.f + __expf(-u)));
            u = acc[mt][nt][2] + t0; vB.x = u * (1.f / (1.f + __expf(-u)));
            u = acc[mt][nt][3] + t1; vB.y = u * (1.f / (1.f + __expf(-u)));
            float* base = d_p + ((size_t)(b * G_ + g) * HW_) * CG_ + cg;
            *(float2*)(base + (size_t)pixA * CG_) = vA;
            *(float2*)(base + (size_t)pixB * CG_) = vB;
        }
    }
}

// ---------------------------------------------------------------------------
// K2a: 3x3 conv partials, 32-channel k-slice, cp.async 4-deep pipeline.
//      Tile stride 35 (conflict-free). grid (2, 4, B*4).
// ---------------------------------------------------------------------------
#define XSTR 35
__global__ __launch_bounds__(256, 4) void k2a_conv3(const float* __restrict__ x,
                                                    const float* __restrict__ w_off) {
    __shared__ float ws[32 * 72];          // [k][tap][oc]
    __shared__ float xbuf[4][18 * XSTR];   // 4-stage pipeline buffers

    int bz = blockIdx.z;
    int b = bz >> 2;
    int split = bz & 3;
    int k_lo = split * 32;
    int h0 = blockIdx.y * 16;
    int w0 = blockIdx.x * 32;
    int tid = threadIdx.y * 16 + threadIdx.x;
    int tx = threadIdx.x;
    int ty = threadIdx.y;

    // weights transposed: ws[(kk*9+t)*8 + oc]
    for (int idx = tid; idx < 32 * 9 * 8; idx += 256) {
        int kk = idx / 72;
        int r = idx - kk * 72;
        int t = r >> 3;
        int oc = r & 7;
        ws[idx] = w_off[oc * (C_ * 9) + (k_lo + kk) * 9 + t];
    }
    // pre-zero pipeline buffers (halo slots stay 0 forever)
    for (int i = tid; i < 4 * 18 * XSTR; i += 256) ((float*)xbuf)[i] = 0.f;

    const float* xb = x + (size_t)b * C_ * HW_ + (size_t)k_lo * HW_;

    // this thread's 3 load slots (fixed across k)
    uint32_t soff[3];
    int goff[3];
    bool sval[3];
    uint32_t sb0 = (uint32_t)__cvta_generic_to_shared(&xbuf[0][0]);
#pragma unroll
    for (int i = 0; i < 3; i++) {
        int idx = tid + i * 256;
        int r = idx / 34, cc = idx - r * 34;
        int h = h0 - 1 + r, w = w0 - 1 + cc;
        soff[i] = (uint32_t)(r * XSTR + cc) * 4u;
        goff[i] = h * W_ + w;
        sval[i] = (idx < 612) && (h >= 0) && (h < H_) && (w >= 0) && (w < W_);
    }

    __syncthreads();   // ws + zeros visible

    // prologue: issue k = 0,1,2 into bufs 0,1,2
#pragma unroll
    for (int kk = 0; kk < 3; kk++) {
        const float* src = xb + (size_t)kk * HW_;
        uint32_t base = sb0 + (uint32_t)kk * (18 * XSTR * 4);
#pragma unroll
        for (int i = 0; i < 3; i++)
            if (sval[i])
                asm volatile("cp.async.ca.shared.global [%0], [%1], 4;"
                             :: "r"(base + soff[i]), "l"(src + goff[i]));
        asm volatile("cp.async.commit_group;");
    }

    float2 acc0[4], acc1[4];
#pragma unroll
    for (int q = 0; q < 4; q++) { acc0[q] = make_float2(0.f, 0.f); acc1[q] = make_float2(0.f, 0.f); }

    for (int k = 0; k < 32; k++) {
        asm volatile("cp.async.wait_group 2;" ::: "memory");
        __syncthreads();

        // issue k+3 (safe: all warps finished computing from this buffer)
        if (k + 3 < 32) {
            const float* src = xb + (size_t)(k + 3) * HW_;
            uint32_t base = sb0 + (uint32_t)((k + 3) & 3) * (18 * XSTR * 4);
#pragma unroll
            for (int i = 0; i < 3; i++)
                if (sval[i])
                    asm volatile("cp.async.ca.shared.global [%0], [%1], 4;"
                                 :: "r"(base + soff[i]), "l"(src + goff[i]));
        }
        asm volatile("cp.async.commit_group;");

        const float* xtc = &xbuf[k & 3][0];
        float xv[3][4];
#pragma unroll
        for (int r = 0; r < 3; r++)
#pragma unroll
            for (int c = 0; c < 4; c++) xv[r][c] = xtc[(ty + r) * XSTR + 2 * tx + c];

        const float* wk = &ws[k * 72];
#pragma unroll
        for (int t = 0; t < 9; t++) {
            int dy = t / 3, dx = t - dy * 3;
            float2 wp[4];
            *(float4*)&wp[0] = *(const float4*)&wk[t * 8 + 0];
            *(float4*)&wp[2] = *(const float4*)&wk[t * 8 + 4];
            float2 xp0 = make_float2(xv[dy][dx], xv[dy][dx]);
            float2 xp1 = make_float2(xv[dy][dx + 1], xv[dy][dx + 1]);
#pragma unroll
            for (int q = 0; q < 4; q++) {
                acc0[q] = fma2(xp0, wp[q], acc0[q]);
                acc1[q] = fma2(xp1, wp[q], acc1[q]);
            }
        }
    }

    int y = h0 + ty;
    int xw = w0 + 2 * tx;
    float* pbase = d_part + (size_t)(split * B_ + b) * 8 * HW_;
#pragma unroll
    for (int q = 0; q < 4; q++) {
        float a0[2] = { acc0[q].x, acc0[q].y };
        float a1[2] = { acc1[q].x, acc1[q].y };
#pragma unroll
        for (int h = 0; h < 2; h++) {
            int oc = q * 2 + h;
            size_t base = (size_t)oc * HW_ + y * W_ + xw;
            pbase[base] = a0[h];
            pbase[base + 1] = a1[h];
        }
    }
}

// ---------------------------------------------------------------------------
// K2b: reduce 4 partials + bias + tanh -> d_off
// ---------------------------------------------------------------------------
__global__ void k2b_reduce(const float* __restrict__ b_off) {
    int i = blockIdx.x * blockDim.x + threadIdx.x;
    const int N4 = B_ * 8 * HW_ / 4;
    if (i >= N4) return;
    int e = i * 4;
    int r = e & (8 * HW_ - 1);
    int b = e / (8 * HW_);
    int oc = r / HW_;

    const float4* p0 = (const float4*)(d_part + ((size_t)(0 * B_ + b) * 8) * HW_ + r);
    const float4* p1 = (const float4*)(d_part + ((size_t)(1 * B_ + b) * 8) * HW_ + r);
    const float4* p2 = (const float4*)(d_part + ((size_t)(2 * B_ + b) * 8) * HW_ + r);
    const float4* p3 = (const float4*)(d_part + ((size_t)(3 * B_ + b) * 8) * HW_ + r);
    float4 v0 = *p0, v1 = *p1, v2 = *p2, v3 = *p3;
    float bo = b_off[oc];
    float4 o;
    o.x = tanhf(v0.x + v1.x + v2.x + v3.x + bo);
    o.y = tanhf(v0.y + v1.y + v2.y + v3.y + bo);
    o.z = tanhf(v0.z + v1.z + v2.z + v3.z + bo);
    o.w = tanhf(v0.w + v1.w + v2.w + v3.w + bo);
    *(float4*)(d_off + e) = o;
}

// ---------------------------------------------------------------------------
// K3: offset upsample + grid_sample, channel-major smem tile, warp=channel,
//     direct coalesced stores (no transpose). Block = 8x32 output px, 512 thr.
// ---------------------------------------------------------------------------
#define CSTR 127
#define K3TW 18
#define K3TH 7
__global__ __launch_bounds__(512) void k3_sample(float* __restrict__ out) {
    int bx = blockIdx.x;           // 0..63
    int ys0 = (bx >> 2) * 8;
    int xs0 = (bx & 3) * 32;
    int g = blockIdx.y;
    int b = blockIdx.z;
    int tid = threadIdx.x;
    int warp = tid >> 5;
    int lane = tid & 31;

    __shared__ float tile[CG_ * CSTR];     // [c][y*18+x], 16.3KB
    __shared__ int   s_r[8][32][4];
    __shared__ float s_f[8][32][2];

    const float SY = 63.0f / 127.0f;
    const float SO = 63.0f / 128.0f;

    int x_lo = max(0, (int)floorf(xs0 * SY - 0.4923f));
    int y_lo = max(0, (int)floorf(ys0 * SY - 0.4923f));

    // cp.async tile load: transpose (pix,c) -> [c][pix]; coalesced gmem reads
    const float* pb = d_p + (size_t)(b * G_ + g) * HW_ * CG_;
    {
        uint32_t st0 = (uint32_t)__cvta_generic_to_shared(&tile[0]);
#pragma unroll
        for (int idx = tid; idx < K3TH * K3TW * CG_; idx += 512) {
            int p = idx >> 5;
            int c = idx & 31;
            int y = min(y_lo + p / K3TW, H_ - 1);
            int xx = min(x_lo + p % K3TW, W_ - 1);
            const float* src = &pb[(y * W_ + xx) * CG_ + c];
            asm volatile("cp.async.ca.shared.global [%0], [%1], 4;"
                         :: "r"(st0 + (uint32_t)(c * CSTR + p) * 4u), "l"(src));
        }
        asm volatile("cp.async.commit_group;");
    }

    // Phase A (overlaps cp.async): 256 threads compute per-pixel coords
    if (tid < 256) {
        int r = tid >> 5;
        int xl = tid & 31;
        int ys = ys0 + r;
        int xs = xs0 + xl;

        float py = ys * SY;
        int y0u = (int)py;
        float wyu = py - y0u;
        int y1u = min(y0u + 1, H_ - 1);
        float px = xs * SY;
        int x0u = (int)px;
        float wxu = px - x0u;
        int x1u = min(x0u + 1, W_ - 1);

        const float* offx = d_off + (size_t)(b * 8 + 2 * g) * HW_;
        const float* offy = offx + HW_;

        float a00 = offx[y0u * W_ + x0u], a01 = offx[y0u * W_ + x1u];
        float a10 = offx[y1u * W_ + x0u], a11 = offx[y1u * W_ + x1u];
        float o_x = (a00 * (1.f - wxu) + a01 * wxu) * (1.f - wyu)
                  + (a10 * (1.f - wxu) + a11 * wxu) * wyu;

        float c00 = offy[y0u * W_ + x0u], c01 = offy[y0u * W_ + x1u];
        float c10 = offy[y1u * W_ + x0u], c11 = offy[y1u * W_ + x1u];
        float o_y = (c00 * (1.f - wxu) + c01 * wxu) * (1.f - wyu)
                  + (c10 * (1.f - wxu) + c11 * wxu) * wyu;

        float ix = fminf(fmaxf(px + o_x * SO, 0.f), (float)(W_ - 1));
        float iy = fminf(fmaxf(py + o_y * SO, 0.f), (float)(H_ - 1));

        int ix0 = (int)ix; if (ix0 > W_ - 1) ix0 = W_ - 1;
        int iy0 = (int)iy; if (iy0 > H_ - 1) iy0 = H_ - 1;
        int ix1 = min(ix0 + 1, W_ - 1);
        int iy1 = min(iy0 + 1, H_ - 1);

        int base = (iy0 - y_lo) * K3TW + (ix0 - x_lo);
        int dxo = ix1 - ix0;
        int dyo = (iy1 - iy0) * K3TW;
        s_r[r][xl][0] = base;
        s_r[r][xl][1] = base + dxo;
        s_r[r][xl][2] = base + dyo;
        s_r[r][xl][3] = base + dyo + dxo;
        s_f[r][xl][0] = ix - ix0;
        s_f[r][xl][1] = iy - iy0;
    }

    asm volatile("cp.async.wait_group 0;" ::: "memory");
    __syncthreads();

    // Phase B: warp w handles channels w and w+16; lane = x pixel; direct store
#pragma unroll
    for (int h = 0; h < 2; h++) {
        int c = warp + h * 16;
        const float* tc = &tile[c * CSTR];
        float* ob = out + ((size_t)(b * C_ + g * CG_ + c) * HS_ + ys0) * WS_ + xs0 + lane;
#pragma unroll
        for (int r = 0; r < 8; r++) {
            int4 rr = *(const int4*)&s_r[r][lane][0];
            float fx = s_f[r][lane][0];
            float fy = s_f[r][lane][1];
            float v00 = tc[rr.x], v01 = tc[rr.y], v10 = tc[rr.z], v11 = tc[rr.w];
            float t0 = v00 * (1.f - fx) + v01 * fx;
            float t1 = v10 * (1.f - fx) + v11 * fx;
            ob[(size_t)r * WS_] = t0 * (1.f - fy) + t1 * fy;
        }
    }
}

// ---------------------------------------------------------------------------
extern "C" void kernel_launch(void* const* d_in, const int* in_sizes, int n_in,
                              void* d_out, int out_size) {
    const float* x      = (const float*)d_in[0];
    const float* w_off  = (const float*)d_in[1];
    const float* b_off  = (const float*)d_in[2];
    const float* w_proj = (const float*)d_in[3];
    const float* gamma  = (const float*)d_in[4];
    const float* beta   = (const float*)d_in[5];
    const float* mean   = (const float*)d_in[6];
    const float* var    = (const float*)d_in[7];
    float* out = (float*)d_out;

    k0_prep<<<16, 1024>>>(w_proj, gamma, beta, mean, var);

    dim3 g2(W_ / 32, H_ / 16, B_ * 4);
    k2a_conv3<<<g2, dim3(16, 16)>>>(x, w_off);

    dim3 g1(HW_ / 128, B_);
    k1_mma<<<g1, 256>>>(x);

    int n4 = B_ * 8 * HW_ / 4;
    k2b_reduce<<<(n4 + 255) / 256, 256>>>(b_off);

    dim3 g3((HS_ / 8) * (WS_ / 32), G_, B_);
    k3_sample<<<g3, 512>>>(out);
}